// round 13
// baseline (speedup 1.0000x reference)
#include <cuda_runtime.h>
#include <cuda_bf16.h>
#include <math.h>
#include <stdint.h>

#define N_NODES 50000
#define N_EDGES 500000
#define IN_DIM  384
#define HID     128
#define NHEAD   8
#define CH      16
#define NLAYER  3
#define OUT_DIM 16

// ================= device scratch =================
__device__ int   g_rowptr[N_NODES + 1];
__device__ int   g_cursor[N_NODES];
__device__ int   g_col[N_EDGES];
__device__ int   g_bsums[64];
__device__ float g_h[(size_t)N_NODES * HID];
__device__ float g_xh[(size_t)N_NODES * HID];
__device__ float g_als[N_NODES * NHEAD];
__device__ float g_ald[N_NODES * NHEAD];
__device__ float g_hid[(size_t)N_NODES * 64];
__device__ __nv_bfloat16 g_hhi[(size_t)N_NODES * HID];
__device__ __nv_bfloat16 g_hlo[(size_t)N_NODES * HID];
// bf16 weights (hi only — 2-term split), K-major
#define B_PROJ_OFF 0
#define B_LIN_OFF  (128 * IN_DIM)
#define B_CLS_OFF  (B_LIN_OFF + NLAYER * 128 * HID)
__device__ __nv_bfloat16 g_bhi[128 * IN_DIM + NLAYER * 128 * HID + 64 * HID];

// ================= CSR build =================
__global__ void zero_rowptr_kernel() {
    int i = blockIdx.x * blockDim.x + threadIdx.x;
    if (i <= N_NODES) g_rowptr[i] = 0;
}
__global__ void hist_kernel(const int* __restrict__ dst) {
    int i = blockIdx.x * blockDim.x + threadIdx.x;
    if (i < N_EDGES) atomicAdd(&g_rowptr[dst[i] + 1], 1);
}
__global__ void scan_block_kernel() {
    __shared__ int s[1024];
    const int n = N_NODES + 1;
    int t = threadIdx.x;
    int gid = blockIdx.x * 1024 + t;
    s[t] = (gid < n) ? g_rowptr[gid] : 0;
    __syncthreads();
    #pragma unroll
    for (int off = 1; off < 1024; off <<= 1) {
        int v = (t >= off) ? s[t - off] : 0;
        __syncthreads();
        s[t] += v;
        __syncthreads();
    }
    if (gid < n) g_rowptr[gid] = s[t];
    if (t == 1023) g_bsums[blockIdx.x] = s[1023];
}
__global__ void scan_sums_kernel(int nb) {
    __shared__ int ws[2];
    int t = threadIdx.x;
    int lane = t & 31, w = t >> 5;
    int v = (t < nb) ? g_bsums[t] : 0;
    int x = v;
    #pragma unroll
    for (int off = 1; off < 32; off <<= 1) {
        int y = __shfl_up_sync(0xffffffffu, x, off);
        if (lane >= off) x += y;
    }
    if (lane == 31) ws[w] = x;
    __syncthreads();
    if (w == 1) x += ws[0];
    if (t < nb) g_bsums[t] = x - v;   // exclusive
}
__global__ void scan_add_kernel() {
    const int n = N_NODES + 1;
    int gid = blockIdx.x * 1024 + threadIdx.x;
    if (gid < n) {
        int v = g_rowptr[gid] + g_bsums[blockIdx.x];
        g_rowptr[gid] = v;
        if (gid < N_NODES) g_cursor[gid] = v;
    }
}
__global__ void scatter_kernel(const int* __restrict__ src, const int* __restrict__ dst) {
    int i = blockIdx.x * blockDim.x + threadIdx.x;
    if (i < N_EDGES) {
        int d = dst[i];
        int pos = atomicAdd(&g_cursor[d], 1);
        g_col[pos] = src[i];
    }
}

// ================= helpers =================
__device__ __forceinline__ uint32_t pack_bf2(float x, float y) {
    __nv_bfloat162 t = __floats2bfloat162_rn(x, y);
    return *reinterpret_cast<uint32_t*>(&t);
}

// ONE launch converts all weights (hi only): proj, lin[3], cls_w1
__global__ void conv_all_kernel(const float* __restrict__ proj_w,
                                const float* __restrict__ lin_w,
                                const float* __restrict__ cls_w1) {
    const int T1 = IN_DIM * 128;
    const int T2 = T1 + NLAYER * HID * 128;
    const int TOT = T2 + HID * 64;
    for (int i = blockIdx.x * blockDim.x + threadIdx.x; i < TOT; i += gridDim.x * blockDim.x) {
        if (i < T1) {
            int k = i >> 7, n = i & 127;
            float v = proj_w[(size_t)k * 128 + n];
            g_bhi[B_PROJ_OFF + (size_t)n * IN_DIM + k] = __float2bfloat16(v);
        } else if (i < T2) {
            int j = i - T1;
            int l = j / (HID * 128);
            j -= l * HID * 128;
            int k = j >> 7, n = j & 127;
            float v = lin_w[(size_t)l * HID * HID + (size_t)k * 128 + n];
            g_bhi[B_LIN_OFF + l * 128 * HID + (size_t)n * HID + k] = __float2bfloat16(v);
        } else {
            int j = i - T2;              // w1 [128][64]
            int k = j >> 6, n = j & 63;
            float v = cls_w1[(size_t)k * 64 + n];
            g_bhi[B_CLS_OFF + (size_t)n * HID + k] = __float2bfloat16(v);
        }
    }
}

// ================= HMMA GEMM (2-term: Ah*B + Al*B), R10 config ==========
// C[M,128] = A[M,K] @ W.  Block 128x128, 8 warps 4(m)x2(n), K-tile 32.
#define ASTRIDE 40   // bf16 elems per smem row (pad -> conflict-free)

__device__ __forceinline__ uint32_t smem_addr_u32(const void* p) {
    return (uint32_t)__cvta_generic_to_shared(p);
}
__device__ __forceinline__ void ldsm_x4(uint32_t* r, uint32_t addr) {
    asm volatile("ldmatrix.sync.aligned.m8n8.x4.shared.b16 {%0,%1,%2,%3}, [%4];"
                 : "=r"(r[0]), "=r"(r[1]), "=r"(r[2]), "=r"(r[3]) : "r"(addr));
}
__device__ __forceinline__ void mma_bf16(float* d, const uint32_t* a, const uint32_t* b) {
    asm volatile(
        "mma.sync.aligned.m16n8k16.row.col.f32.bf16.bf16.f32 "
        "{%0,%1,%2,%3}, {%4,%5,%6,%7}, {%8,%9}, {%0,%1,%2,%3};"
        : "+f"(d[0]), "+f"(d[1]), "+f"(d[2]), "+f"(d[3])
        : "r"(a[0]), "r"(a[1]), "r"(a[2]), "r"(a[3]), "r"(b[0]), "r"(b[1]));
}

template<int MODE>
__global__ __launch_bounds__(256, 2)
void gemm_mma(const void* __restrict__ A_, const __nv_bfloat16* __restrict__ Alo_,
              const __nv_bfloat16* __restrict__ Bhi,
              const float* __restrict__ bias,
              const float* __restrict__ att_s, const float* __restrict__ att_d,
              float* __restrict__ C,
              __nv_bfloat16* __restrict__ Chi, __nv_bfloat16* __restrict__ Clo,
              int M, int K)
{
    __shared__ __align__(16) __nv_bfloat16 sAh[128 * ASTRIDE];
    __shared__ __align__(16) __nv_bfloat16 sAl[128 * ASTRIDE];
    __shared__ __align__(16) __nv_bfloat16 sBh[128 * ASTRIDE];

    const int tid  = threadIdx.x;
    const int wid  = tid >> 5, lane = tid & 31;
    const int wr   = wid >> 1, wc = wid & 1;     // warp 4x2 grid
    const int m0   = blockIdx.x * 128;

    const int r  = tid >> 1;
    const int kh = (tid & 1) * 16;
    const int grow = m0 + r;
    const bool valid = grow < M;

    float acc[2][8][4];
    #pragma unroll
    for (int mt = 0; mt < 2; ++mt)
        #pragma unroll
        for (int nt = 0; nt < 8; ++nt)
            #pragma unroll
            for (int j = 0; j < 4; ++j) acc[mt][nt][j] = 0.f;

    const uint32_t aAh = smem_addr_u32(sAh);
    const uint32_t aAl = smem_addr_u32(sAl);
    const uint32_t aBh = smem_addr_u32(sBh);
    const int a_row = wr * 32 + (lane & 15);
    const int a_kof = (lane >> 4) * 8;
    const int b_row = wc * 64 + (lane & 7) + ((lane >> 4) << 3);
    const int b_kof = ((lane >> 3) & 1) * 8;

    const int nkt = K >> 5;
    for (int kt = 0; kt < nkt; ++kt) {
        __syncthreads();
        // ---- fill A ----
        if (MODE == 0) {
            const float* ap = (const float*)A_ + (size_t)grow * K + kt * 32 + kh;
            float4 f0, f1, f2, f3;
            if (valid) {
                f0 = *(const float4*)(ap + 0);
                f1 = *(const float4*)(ap + 4);
                f2 = *(const float4*)(ap + 8);
                f3 = *(const float4*)(ap + 12);
            } else {
                f0 = make_float4(0.f, 0.f, 0.f, 0.f);
                f1 = f0; f2 = f0; f3 = f0;
            }
            uint4 uh0, uh1, ul0, ul1;
            uh0.x = pack_bf2(f0.x, f0.y); uh0.y = pack_bf2(f0.z, f0.w);
            uh0.z = pack_bf2(f1.x, f1.y); uh0.w = pack_bf2(f1.z, f1.w);
            uh1.x = pack_bf2(f2.x, f2.y); uh1.y = pack_bf2(f2.z, f2.w);
            uh1.z = pack_bf2(f3.x, f3.y); uh1.w = pack_bf2(f3.z, f3.w);
            const __nv_bfloat162* hp0 = (const __nv_bfloat162*)&uh0;
            const __nv_bfloat162* hp1 = (const __nv_bfloat162*)&uh1;
            float2 h;
            h = __bfloat1622float2(hp0[0]); ul0.x = pack_bf2(f0.x - h.x, f0.y - h.y);
            h = __bfloat1622float2(hp0[1]); ul0.y = pack_bf2(f0.z - h.x, f0.w - h.y);
            h = __bfloat1622float2(hp0[2]); ul0.z = pack_bf2(f1.x - h.x, f1.y - h.y);
            h = __bfloat1622float2(hp0[3]); ul0.w = pack_bf2(f1.z - h.x, f1.w - h.y);
            h = __bfloat1622float2(hp1[0]); ul1.x = pack_bf2(f2.x - h.x, f2.y - h.y);
            h = __bfloat1622float2(hp1[1]); ul1.y = pack_bf2(f2.z - h.x, f2.w - h.y);
            h = __bfloat1622float2(hp1[2]); ul1.z = pack_bf2(f3.x - h.x, f3.y - h.y);
            h = __bfloat1622float2(hp1[3]); ul1.w = pack_bf2(f3.z - h.x, f3.w - h.y);
            *(uint4*)&sAh[r * ASTRIDE + kh]     = uh0;
            *(uint4*)&sAh[r * ASTRIDE + kh + 8] = uh1;
            *(uint4*)&sAl[r * ASTRIDE + kh]     = ul0;
            *(uint4*)&sAl[r * ASTRIDE + kh + 8] = ul1;
        } else {
            const uint4 z = make_uint4(0u, 0u, 0u, 0u);
            const __nv_bfloat16* ah = (const __nv_bfloat16*)A_ + (size_t)grow * K + kt * 32 + kh;
            const __nv_bfloat16* al = Alo_ + (size_t)grow * K + kt * 32 + kh;
            uint4 h0 = valid ? *(const uint4*)(ah)     : z;
            uint4 h1 = valid ? *(const uint4*)(ah + 8) : z;
            uint4 l0 = valid ? *(const uint4*)(al)     : z;
            uint4 l1 = valid ? *(const uint4*)(al + 8) : z;
            *(uint4*)&sAh[r * ASTRIDE + kh]     = h0;
            *(uint4*)&sAh[r * ASTRIDE + kh + 8] = h1;
            *(uint4*)&sAl[r * ASTRIDE + kh]     = l0;
            *(uint4*)&sAl[r * ASTRIDE + kh + 8] = l1;
        }
        // ---- fill B (bf16, K-major) ----
        {
            const __nv_bfloat16* bh = Bhi + (size_t)r * K + kt * 32 + kh;
            *(uint4*)&sBh[r * ASTRIDE + kh]     = *(const uint4*)(bh + 0);
            *(uint4*)&sBh[r * ASTRIDE + kh + 8] = *(const uint4*)(bh + 8);
        }
        __syncthreads();

        #pragma unroll
        for (int ks = 0; ks < 2; ++ks) {
            const uint32_t aoff = (uint32_t)((a_row * ASTRIDE + ks * 16 + a_kof) * 2);
            const uint32_t boff = (uint32_t)((b_row * ASTRIDE + ks * 16 + b_kof) * 2);
            uint32_t ah[2][4], al[2][4], bb[8][2];
            ldsm_x4(ah[0], aAh + aoff);
            ldsm_x4(ah[1], aAh + aoff + 16 * ASTRIDE * 2);
            ldsm_x4(al[0], aAl + aoff);
            ldsm_x4(al[1], aAl + aoff + 16 * ASTRIDE * 2);
            #pragma unroll
            for (int p = 0; p < 4; ++p)
                ldsm_x4(&bb[p * 2][0], aBh + boff + (uint32_t)(p * 16 * ASTRIDE * 2));
            #pragma unroll
            for (int mt = 0; mt < 2; ++mt)
                #pragma unroll
                for (int nt = 0; nt < 8; ++nt) {
                    mma_bf16(acc[mt][nt], ah[mt], bb[nt]);
                    mma_bf16(acc[mt][nt], al[mt], bb[nt]);
                }
        }
    }

    // ---- epilogue ----
    const int colb = wc * 64 + (lane & 3) * 2;
    const int rowb = m0 + wr * 32 + (lane >> 2);
    #pragma unroll
    for (int mt = 0; mt < 2; ++mt) {
        #pragma unroll
        for (int nt = 0; nt < 8; ++nt) {
            int col = colb + nt * 8;
            float2 v0, v1;
            v0.x = acc[mt][nt][0]; v0.y = acc[mt][nt][1];
            v1.x = acc[mt][nt][2]; v1.y = acc[mt][nt][3];
            if (MODE == 0) {
                float bx = __ldg(&bias[col]), by = __ldg(&bias[col + 1]);
                v0.x = fmaxf(v0.x + bx, 0.f); v0.y = fmaxf(v0.y + by, 0.f);
                v1.x = fmaxf(v1.x + bx, 0.f); v1.y = fmaxf(v1.y + by, 0.f);
                acc[mt][nt][0] = v0.x; acc[mt][nt][1] = v0.y;
                acc[mt][nt][2] = v1.x; acc[mt][nt][3] = v1.y;
            }
            int row0 = rowb + mt * 16;
            int row1 = row0 + 8;
            if (row0 < M) {
                *(float2*)&C[(size_t)row0 * 128 + col] = v0;
                if (MODE == 0) {
                    uint32_t hh = pack_bf2(v0.x, v0.y);
                    float2 f = __bfloat1622float2(*(__nv_bfloat162*)&hh);
                    uint32_t ll = pack_bf2(v0.x - f.x, v0.y - f.y);
                    *(uint32_t*)&Chi[(size_t)row0 * 128 + col] = hh;
                    *(uint32_t*)&Clo[(size_t)row0 * 128 + col] = ll;
                }
            }
            if (row1 < M) {
                *(float2*)&C[(size_t)row1 * 128 + col] = v1;
                if (MODE == 0) {
                    uint32_t hh = pack_bf2(v1.x, v1.y);
                    float2 f = __bfloat1622float2(*(__nv_bfloat162*)&hh);
                    uint32_t ll = pack_bf2(v1.x - f.x, v1.y - f.y);
                    *(uint32_t*)&Chi[(size_t)row1 * 128 + col] = hh;
                    *(uint32_t*)&Clo[(size_t)row1 * 128 + col] = ll;
                }
            }
        }
    }

    if (MODE == 1) {
        // ---- fused attention logits (att vectors hoisted) ----
        float as_r[4][2][2], ad_r[4][2][2];   // [hl][jb][ntb]
        #pragma unroll
        for (int hl = 0; hl < 4; ++hl)
            #pragma unroll
            for (int jb = 0; jb < 2; ++jb)
                #pragma unroll
                for (int ntb = 0; ntb < 2; ++ntb) {
                    int cmod = (lane & 3) * 2 + jb + 8 * ntb;
                    as_r[hl][jb][ntb] = __ldg(&att_s[(wc * 4 + hl) * 16 + cmod]);
                    ad_r[hl][jb][ntb] = __ldg(&att_d[(wc * 4 + hl) * 16 + cmod]);
                }
        #pragma unroll
        for (int mt = 0; mt < 2; ++mt) {
            float ss[2][4], dd[2][4];
            #pragma unroll
            for (int a = 0; a < 2; ++a)
                #pragma unroll
                for (int b = 0; b < 4; ++b) { ss[a][b] = 0.f; dd[a][b] = 0.f; }
            #pragma unroll
            for (int nt = 0; nt < 8; ++nt) {
                int hl = nt >> 1, ntb = nt & 1;
                #pragma unroll
                for (int j = 0; j < 4; ++j) {
                    int jb = j & 1, rj = j >> 1;
                    ss[rj][hl] = fmaf(acc[mt][nt][j], as_r[hl][jb][ntb], ss[rj][hl]);
                    dd[rj][hl] = fmaf(acc[mt][nt][j], ad_r[hl][jb][ntb], dd[rj][hl]);
                }
            }
            #pragma unroll
            for (int rj = 0; rj < 2; ++rj)
                #pragma unroll
                for (int hl = 0; hl < 4; ++hl) {
                    ss[rj][hl] += __shfl_xor_sync(0xffffffffu, ss[rj][hl], 1);
                    ss[rj][hl] += __shfl_xor_sync(0xffffffffu, ss[rj][hl], 2);
                    dd[rj][hl] += __shfl_xor_sync(0xffffffffu, dd[rj][hl], 1);
                    dd[rj][hl] += __shfl_xor_sync(0xffffffffu, dd[rj][hl], 2);
                }
            if ((lane & 3) == 0) {
                #pragma unroll
                for (int rj = 0; rj < 2; ++rj) {
                    int row = rowb + mt * 16 + rj * 8;
                    if (row < M) {
                        #pragma unroll
                        for (int hl = 0; hl < 4; ++hl) {
                            g_als[row * 8 + wc * 4 + hl] = ss[rj][hl];
                            g_ald[row * 8 + wc * 4 + hl] = dd[rj][hl];
                        }
                    }
                }
            }
        }
    }
}

// ================= classifier hidden layer via HMMA =================
#define CSTRIDE 40
__global__ __launch_bounds__(256, 2)
void cls_hid_gemm(const __nv_bfloat16* __restrict__ Ahi, const __nv_bfloat16* __restrict__ Alo,
                  const __nv_bfloat16* __restrict__ Bh, const float* __restrict__ b1,
                  float* __restrict__ Hid, int M)
{
    __shared__ __align__(16) __nv_bfloat16 sAh[128 * CSTRIDE];
    __shared__ __align__(16) __nv_bfloat16 sAl[128 * CSTRIDE];
    __shared__ __align__(16) __nv_bfloat16 sB[64 * CSTRIDE];

    const int tid = threadIdx.x;
    const int wid = tid >> 5, lane = tid & 31;
    const int wr = wid >> 1, wc = wid & 1;
    const int m0 = blockIdx.x * 128;
    const int r = tid >> 1;
    const int kh = (tid & 1) * 16;
    const int grow = m0 + r;
    const bool valid = grow < M;

    float acc[2][4][4];
    #pragma unroll
    for (int mt = 0; mt < 2; ++mt)
        #pragma unroll
        for (int nt = 0; nt < 4; ++nt)
            #pragma unroll
            for (int j = 0; j < 4; ++j) acc[mt][nt][j] = 0.f;

    const uint32_t aAh = smem_addr_u32(sAh);
    const uint32_t aAl = smem_addr_u32(sAl);
    const uint32_t aB  = smem_addr_u32(sB);
    const int a_row = wr * 32 + (lane & 15);
    const int a_kof = (lane >> 4) * 8;
    const int b_row = wc * 32 + (lane & 7) + ((lane >> 4) << 3);
    const int b_kof = ((lane >> 3) & 1) * 8;

    #pragma unroll
    for (int kt = 0; kt < 4; ++kt) {
        __syncthreads();
        {
            const uint4 z = make_uint4(0u, 0u, 0u, 0u);
            const __nv_bfloat16* ah = Ahi + (size_t)grow * HID + kt * 32 + kh;
            const __nv_bfloat16* al = Alo + (size_t)grow * HID + kt * 32 + kh;
            uint4 h0 = valid ? *(const uint4*)(ah)     : z;
            uint4 h1 = valid ? *(const uint4*)(ah + 8) : z;
            uint4 l0 = valid ? *(const uint4*)(al)     : z;
            uint4 l1 = valid ? *(const uint4*)(al + 8) : z;
            *(uint4*)&sAh[r * CSTRIDE + kh]     = h0;
            *(uint4*)&sAh[r * CSTRIDE + kh + 8] = h1;
            *(uint4*)&sAl[r * CSTRIDE + kh]     = l0;
            *(uint4*)&sAl[r * CSTRIDE + kh + 8] = l1;
        }
        if (tid < 128) {
            int br = tid >> 1;
            const __nv_bfloat16* bp = Bh + (size_t)br * HID + kt * 32 + kh;
            *(uint4*)&sB[br * CSTRIDE + kh]     = *(const uint4*)(bp + 0);
            *(uint4*)&sB[br * CSTRIDE + kh + 8] = *(const uint4*)(bp + 8);
        }
        __syncthreads();

        #pragma unroll
        for (int ks = 0; ks < 2; ++ks) {
            const uint32_t aoff = (uint32_t)((a_row * CSTRIDE + ks * 16 + a_kof) * 2);
            const uint32_t boff = (uint32_t)((b_row * CSTRIDE + ks * 16 + b_kof) * 2);
            uint32_t ah[2][4], al[2][4], bb[4][2];
            ldsm_x4(ah[0], aAh + aoff);
            ldsm_x4(ah[1], aAh + aoff + 16 * CSTRIDE * 2);
            ldsm_x4(al[0], aAl + aoff);
            ldsm_x4(al[1], aAl + aoff + 16 * CSTRIDE * 2);
            ldsm_x4(&bb[0][0], aB + boff);
            ldsm_x4(&bb[2][0], aB + boff + (uint32_t)(16 * CSTRIDE * 2));
            #pragma unroll
            for (int mt = 0; mt < 2; ++mt)
                #pragma unroll
                for (int nt = 0; nt < 4; ++nt) {
                    mma_bf16(acc[mt][nt], ah[mt], bb[nt]);
                    mma_bf16(acc[mt][nt], al[mt], bb[nt]);
                }
        }
    }

    const int colb = wc * 32 + (lane & 3) * 2;
    const int rowb = m0 + wr * 32 + (lane >> 2);
    #pragma unroll
    for (int mt = 0; mt < 2; ++mt) {
        #pragma unroll
        for (int nt = 0; nt < 4; ++nt) {
            int col = colb + nt * 8;
            float bx = __ldg(&b1[col]), by = __ldg(&b1[col + 1]);
            float2 v0, v1;
            v0.x = fmaxf(acc[mt][nt][0] + bx, 0.f);
            v0.y = fmaxf(acc[mt][nt][1] + by, 0.f);
            v1.x = fmaxf(acc[mt][nt][2] + bx, 0.f);
            v1.y = fmaxf(acc[mt][nt][3] + by, 0.f);
            int row0 = rowb + mt * 16;
            int row1 = row0 + 8;
            if (row0 < M) *(float2*)&Hid[(size_t)row0 * 64 + col] = v0;
            if (row1 < M) *(float2*)&Hid[(size_t)row1 * 64 + col] = v1;
        }
    }
}

// ================= logits + log_softmax (warp per row) =================
__global__ __launch_bounds__(256)
void logits_kernel(const float* __restrict__ hid,
                   const float* __restrict__ w2, const float* __restrict__ b2,
                   float* __restrict__ out)
{
    __shared__ float s_w2[64 * OUT_DIM];
    __shared__ float s_b2[OUT_DIM];
    __shared__ float s_hid[8][64];

    int tid = threadIdx.x;
    for (int i = tid; i < 64 * OUT_DIM; i += 256) s_w2[i] = w2[i];
    if (tid < OUT_DIM) s_b2[tid] = b2[tid];
    __syncthreads();

    int warp = tid >> 5, lane = tid & 31;
    int stride = gridDim.x * 8;
    for (int row = blockIdx.x * 8 + warp; row < N_NODES; row += stride) {
        float2 hv = *(const float2*)&hid[(size_t)row * 64 + lane * 2];
        *(float2*)&s_hid[warp][lane * 2] = hv;
        __syncwarp();
        int o = lane & 15;
        int kbase = (lane >> 4) * 32;
        float part = 0.f;
        #pragma unroll 8
        for (int k = 0; k < 32; ++k)
            part = fmaf(s_hid[warp][kbase + k], s_w2[(kbase + k) * OUT_DIM + o], part);
        part += __shfl_xor_sync(0xffffffffu, part, 16);
        float logit = part + s_b2[o];
        float mx = logit;
        #pragma unroll
        for (int off = 8; off; off >>= 1)
            mx = fmaxf(mx, __shfl_xor_sync(0xffffffffu, mx, off));
        float ex = __expf(logit - mx);
        float sm = ex;
        #pragma unroll
        for (int off = 8; off; off >>= 1)
            sm += __shfl_xor_sync(0xffffffffu, sm, off);
        float res = logit - mx - logf(sm);
        if (lane < 16) out[(size_t)row * OUT_DIM + lane] = res;
        __syncwarp();
    }
}

// ================= GAT aggregation (warp per dst, pipelined) =================
__global__ __launch_bounds__(256)
void gat_aggregate(const float* __restrict__ xh,
                   const float* __restrict__ gat_b,
                   const float* __restrict__ ln_g,
                   const float* __restrict__ ln_b,
                   float* __restrict__ h,
                   __nv_bfloat16* __restrict__ hhi,
                   __nv_bfloat16* __restrict__ hlo)
{
    int w = (blockIdx.x * blockDim.x + threadIdx.x) >> 5;
    if (w >= N_NODES) return;
    int lane = threadIdx.x & 31;
    int hd = lane >> 2;
    int f = lane * 4;

    float a_d = g_ald[w * NHEAD + hd];
    float e0 = g_als[w * NHEAD + hd] + a_d;
    e0 = fmaxf(e0, 0.2f * e0);
    float m = e0;
    float denom = 1.0f;
    float4 acc = *(const float4*)&xh[(size_t)w * HID + f];

    int beg = g_rowptr[w], end = g_rowptr[w + 1];
    if (beg < end) {
        // software pipeline: stage holds (e, v) for the current edge while
        // next edge's index+loads are issued before the serial update chain.
        int   sA = __ldg(&g_col[beg]);
        float eA = __ldg(&g_als[sA * NHEAD + hd]);
        float4 vA = *(const float4*)&xh[(size_t)sA * HID + f];
        for (int i = beg; i < end; ++i) {
            // issue next edge's loads first (independent of update chain)
            float eB = 0.f;
            float4 vB = vA;
            if (i + 1 < end) {
                int sB = __ldg(&g_col[i + 1]);
                eB = __ldg(&g_als[sB * NHEAD + hd]);
                vB = *(const float4*)&xh[(size_t)sB * HID + f];
            }
            // update with current edge
            float e2 = eA + a_d;
            e2 = fmaxf(e2, 0.2f * e2);
            float mn = fmaxf(m, e2);
            float sc = __expf(m - mn);
            float p  = __expf(e2 - mn);
            acc.x = acc.x * sc + p * vA.x;
            acc.y = acc.y * sc + p * vA.y;
            acc.z = acc.z * sc + p * vA.z;
            acc.w = acc.w * sc + p * vA.w;
            denom = denom * sc + p;
            m = mn;
            eA = eB;
            vA = vB;
        }
    }

    float inv = 1.0f / denom;
    float4 r  = *(const float4*)&h[(size_t)w * HID + f];
    float4 gb = *(const float4*)&gat_b[f];
    float v0 = fmaf(acc.x, inv, gb.x + r.x);
    float v1 = fmaf(acc.y, inv, gb.y + r.y);
    float v2 = fmaf(acc.z, inv, gb.z + r.z);
    float v3 = fmaf(acc.w, inv, gb.w + r.w);

    float sum = v0 + v1 + v2 + v3;
    float sq  = v0 * v0 + v1 * v1 + v2 * v2 + v3 * v3;
    #pragma unroll
    for (int off = 16; off; off >>= 1) {
        sum += __shfl_xor_sync(0xffffffffu, sum, off);
        sq  += __shfl_xor_sync(0xffffffffu, sq,  off);
    }
    float mean = sum * (1.0f / 128.0f);
    float var  = sq  * (1.0f / 128.0f) - mean * mean;
    float rs = rsqrtf(var + 1e-5f);

    float4 g4 = *(const float4*)&ln_g[f];
    float4 b4 = *(const float4*)&ln_b[f];
    float4 o;
    o.x = fmaxf((v0 - mean) * rs * g4.x + b4.x, 0.f);
    o.y = fmaxf((v1 - mean) * rs * g4.y + b4.y, 0.f);
    o.z = fmaxf((v2 - mean) * rs * g4.z + b4.z, 0.f);
    o.w = fmaxf((v3 - mean) * rs * g4.w + b4.w, 0.f);
    *(float4*)&h[(size_t)w * HID + f] = o;

    uint32_t h0 = pack_bf2(o.x, o.y), h1 = pack_bf2(o.z, o.w);
    float2 f0 = __bfloat1622float2(*(__nv_bfloat162*)&h0);
    float2 f1 = __bfloat1622float2(*(__nv_bfloat162*)&h1);
    uint32_t l0 = pack_bf2(o.x - f0.x, o.y - f0.y);
    uint32_t l1 = pack_bf2(o.z - f1.x, o.w - f1.y);
    uint2 uh; uh.x = h0; uh.y = h1;
    uint2 ul; ul.x = l0; ul.y = l1;
    *(uint2*)&hhi[(size_t)w * HID + f] = uh;
    *(uint2*)&hlo[(size_t)w * HID + f] = ul;
}

// ================= launch =================
extern "C" void kernel_launch(void* const* d_in, const int* in_sizes, int n_in,
                              void* d_out, int out_size)
{
    const float* x       = (const float*)d_in[0];
    const int*   ei      = (const int*)  d_in[1];
    const float* proj_w  = (const float*)d_in[2];
    const float* proj_b  = (const float*)d_in[3];
    const float* lin_w   = (const float*)d_in[4];
    const float* att_src = (const float*)d_in[5];
    const float* att_dst = (const float*)d_in[6];
    const float* gat_b   = (const float*)d_in[7];
    const float* ln_g    = (const float*)d_in[8];
    const float* ln_b    = (const float*)d_in[9];
    const float* cls_w1  = (const float*)d_in[10];
    const float* cls_b1  = (const float*)d_in[11];
    const float* cls_w2  = (const float*)d_in[12];
    const float* cls_b2  = (const float*)d_in[13];
    float* out = (float*)d_out;

    const int* src = ei;
    const int* dst = ei + N_EDGES;

    float *h_ptr = nullptr, *xh_ptr = nullptr, *hid_ptr = nullptr;
    __nv_bfloat16 *bhi = nullptr, *hhi = nullptr, *hlo = nullptr;
    cudaGetSymbolAddress((void**)&h_ptr, g_h);
    cudaGetSymbolAddress((void**)&xh_ptr, g_xh);
    cudaGetSymbolAddress((void**)&hid_ptr, g_hid);
    cudaGetSymbolAddress((void**)&bhi, g_bhi);
    cudaGetSymbolAddress((void**)&hhi, g_hhi);
    cudaGetSymbolAddress((void**)&hlo, g_hlo);

    const int GEMM_GRID = (N_NODES + 127) / 128;  // 391
    const int SCAN_BLOCKS = (N_NODES + 1 + 1023) / 1024;  // 49

    // my#1-3: conversions + independent CSR prefix
    conv_all_kernel<<<128, 256>>>(proj_w, lin_w, cls_w1);
    zero_rowptr_kernel<<<(N_NODES + 1 + 255) / 256, 256>>>();
    hist_kernel<<<(N_EDGES + 255) / 256, 256>>>(dst);

    // my#4 (ncu-profiled): projection GEMM  h = relu(x @ proj_w + b)
    gemm_mma<0><<<GEMM_GRID, 256>>>(
        x, nullptr, bhi + B_PROJ_OFF, proj_b,
        nullptr, nullptr, h_ptr, hhi, hlo, N_NODES, IN_DIM);

    // layer-0 GEMM + fused attention logits
    gemm_mma<1><<<GEMM_GRID, 256>>>(
        hhi, hlo, bhi + B_LIN_OFF, nullptr,
        att_src, att_dst, xh_ptr, nullptr, nullptr, N_NODES, HID);

    // CSR build tail
    scan_block_kernel<<<SCAN_BLOCKS, 1024>>>();
    scan_sums_kernel<<<1, 64>>>(SCAN_BLOCKS);
    scan_add_kernel<<<SCAN_BLOCKS, 1024>>>();
    scatter_kernel<<<(N_EDGES + 255) / 256, 256>>>(src, dst);

    // layer 0 aggregation
    gat_aggregate<<<N_NODES / 8, 256>>>(
        xh_ptr, gat_b, ln_g, ln_b, h_ptr, hhi, hlo);

    // layers 1..2
    for (int l = 1; l < NLAYER; ++l) {
        gemm_mma<1><<<GEMM_GRID, 256>>>(
            hhi, hlo, bhi + B_LIN_OFF + l * 128 * HID,
            nullptr, att_src + l * NHEAD * CH, att_dst + l * NHEAD * CH,
            xh_ptr, nullptr, nullptr, N_NODES, HID);
        gat_aggregate<<<N_NODES / 8, 256>>>(
            xh_ptr, gat_b + l * HID, ln_g + l * HID, ln_b + l * HID, h_ptr, hhi, hlo);
    }

    // classifier: hidden layer on tensor cores, then tiny logits+log_softmax
    cls_hid_gemm<<<GEMM_GRID, 256>>>(hhi, hlo, bhi + B_CLS_OFF, cls_b1, hid_ptr, N_NODES);
    logits_kernel<<<592, 256>>>(hid_ptr, cls_w2, cls_b2, out);
}

// round 15
// speedup vs baseline: 1.0791x; 1.0791x over previous
#include <cuda_runtime.h>
#include <cuda_bf16.h>
#include <cuda_fp16.h>
#include <math.h>
#include <stdint.h>

#define N_NODES 50000
#define N_EDGES 500000
#define IN_DIM  384
#define HID     128
#define NHEAD   8
#define CH      16
#define NLAYER  3
#define OUT_DIM 16

// ================= device scratch =================
__device__ int   g_rowptr[N_NODES + 1];
__device__ int   g_cursor[N_NODES];
__device__ int   g_col[N_EDGES];
__device__ int   g_bsums[64];
__device__ float g_h[(size_t)N_NODES * HID];
__device__ __half g_xhh[(size_t)N_NODES * HID];   // fp16 xh (GEMM out, aggregate in)
__device__ float g_als[N_NODES * NHEAD];
__device__ float g_ald[N_NODES * NHEAD];
__device__ float g_hid[(size_t)N_NODES * 64];
__device__ __nv_bfloat16 g_hhi[(size_t)N_NODES * HID];
__device__ __nv_bfloat16 g_hlo[(size_t)N_NODES * HID];
// bf16 weights (hi only — 2-term split), K-major
#define B_PROJ_OFF 0
#define B_LIN_OFF  (128 * IN_DIM)
#define B_CLS_OFF  (B_LIN_OFF + NLAYER * 128 * HID)
__device__ __nv_bfloat16 g_bhi[128 * IN_DIM + NLAYER * 128 * HID + 64 * HID];

// ================= CSR build =================
__global__ void zero_rowptr_kernel() {
    int i = blockIdx.x * blockDim.x + threadIdx.x;
    if (i <= N_NODES) g_rowptr[i] = 0;
}
__global__ void hist_kernel(const int* __restrict__ dst) {
    int i = blockIdx.x * blockDim.x + threadIdx.x;
    if (i < N_EDGES) atomicAdd(&g_rowptr[dst[i] + 1], 1);
}
__global__ void scan_block_kernel() {
    __shared__ int s[1024];
    const int n = N_NODES + 1;
    int t = threadIdx.x;
    int gid = blockIdx.x * 1024 + t;
    s[t] = (gid < n) ? g_rowptr[gid] : 0;
    __syncthreads();
    #pragma unroll
    for (int off = 1; off < 1024; off <<= 1) {
        int v = (t >= off) ? s[t - off] : 0;
        __syncthreads();
        s[t] += v;
        __syncthreads();
    }
    if (gid < n) g_rowptr[gid] = s[t];
    if (t == 1023) g_bsums[blockIdx.x] = s[1023];
}
__global__ void scan_sums_kernel(int nb) {
    __shared__ int ws[2];
    int t = threadIdx.x;
    int lane = t & 31, w = t >> 5;
    int v = (t < nb) ? g_bsums[t] : 0;
    int x = v;
    #pragma unroll
    for (int off = 1; off < 32; off <<= 1) {
        int y = __shfl_up_sync(0xffffffffu, x, off);
        if (lane >= off) x += y;
    }
    if (lane == 31) ws[w] = x;
    __syncthreads();
    if (w == 1) x += ws[0];
    if (t < nb) g_bsums[t] = x - v;   // exclusive
}
__global__ void scan_add_kernel() {
    const int n = N_NODES + 1;
    int gid = blockIdx.x * 1024 + threadIdx.x;
    if (gid < n) {
        int v = g_rowptr[gid] + g_bsums[blockIdx.x];
        g_rowptr[gid] = v;
        if (gid < N_NODES) g_cursor[gid] = v;
    }
}
__global__ void scatter_kernel(const int* __restrict__ src, const int* __restrict__ dst) {
    int i = blockIdx.x * blockDim.x + threadIdx.x;
    if (i < N_EDGES) {
        int d = dst[i];
        int pos = atomicAdd(&g_cursor[d], 1);
        g_col[pos] = src[i];
    }
}

// ================= helpers =================
__device__ __forceinline__ uint32_t pack_bf2(float x, float y) {
    __nv_bfloat162 t = __floats2bfloat162_rn(x, y);
    return *reinterpret_cast<uint32_t*>(&t);
}

// ONE launch converts all weights (hi only): proj, lin[3], cls_w1
__global__ void conv_all_kernel(const float* __restrict__ proj_w,
                                const float* __restrict__ lin_w,
                                const float* __restrict__ cls_w1) {
    const int T1 = IN_DIM * 128;
    const int T2 = T1 + NLAYER * HID * 128;
    const int TOT = T2 + HID * 64;
    for (int i = blockIdx.x * blockDim.x + threadIdx.x; i < TOT; i += gridDim.x * blockDim.x) {
        if (i < T1) {
            int k = i >> 7, n = i & 127;
            float v = proj_w[(size_t)k * 128 + n];
            g_bhi[B_PROJ_OFF + (size_t)n * IN_DIM + k] = __float2bfloat16(v);
        } else if (i < T2) {
            int j = i - T1;
            int l = j / (HID * 128);
            j -= l * HID * 128;
            int k = j >> 7, n = j & 127;
            float v = lin_w[(size_t)l * HID * HID + (size_t)k * 128 + n];
            g_bhi[B_LIN_OFF + l * 128 * HID + (size_t)n * HID + k] = __float2bfloat16(v);
        } else {
            int j = i - T2;              // w1 [128][64]
            int k = j >> 6, n = j & 63;
            float v = cls_w1[(size_t)k * 64 + n];
            g_bhi[B_CLS_OFF + (size_t)n * HID + k] = __float2bfloat16(v);
        }
    }
}

// ================= HMMA GEMM (2-term: Ah*B + Al*B), R10 config ==========
// C[M,128] = A[M,K] @ W.  Block 128x128, 8 warps 4(m)x2(n), K-tile 32.
// MODE 0: A fp32 split on the fly; out fp32 C + bf16 hi/lo split.
// MODE 1: A pre-split bf16; out fp16 Cxh + fused attn logits.
#define ASTRIDE 40   // bf16 elems per smem row (pad -> conflict-free)

__device__ __forceinline__ uint32_t smem_addr_u32(const void* p) {
    return (uint32_t)__cvta_generic_to_shared(p);
}
__device__ __forceinline__ void ldsm_x4(uint32_t* r, uint32_t addr) {
    asm volatile("ldmatrix.sync.aligned.m8n8.x4.shared.b16 {%0,%1,%2,%3}, [%4];"
                 : "=r"(r[0]), "=r"(r[1]), "=r"(r[2]), "=r"(r[3]) : "r"(addr));
}
__device__ __forceinline__ void mma_bf16(float* d, const uint32_t* a, const uint32_t* b) {
    asm volatile(
        "mma.sync.aligned.m16n8k16.row.col.f32.bf16.bf16.f32 "
        "{%0,%1,%2,%3}, {%4,%5,%6,%7}, {%8,%9}, {%0,%1,%2,%3};"
        : "+f"(d[0]), "+f"(d[1]), "+f"(d[2]), "+f"(d[3])
        : "r"(a[0]), "r"(a[1]), "r"(a[2]), "r"(a[3]), "r"(b[0]), "r"(b[1]));
}

template<int MODE>
__global__ __launch_bounds__(256, 2)
void gemm_mma(const void* __restrict__ A_, const __nv_bfloat16* __restrict__ Alo_,
              const __nv_bfloat16* __restrict__ Bhi,
              const float* __restrict__ bias,
              const float* __restrict__ att_s, const float* __restrict__ att_d,
              float* __restrict__ C, __half* __restrict__ Cxh,
              __nv_bfloat16* __restrict__ Chi, __nv_bfloat16* __restrict__ Clo,
              int M, int K)
{
    __shared__ __align__(16) __nv_bfloat16 sAh[128 * ASTRIDE];
    __shared__ __align__(16) __nv_bfloat16 sAl[128 * ASTRIDE];
    __shared__ __align__(16) __nv_bfloat16 sBh[128 * ASTRIDE];

    const int tid  = threadIdx.x;
    const int wid  = tid >> 5, lane = tid & 31;
    const int wr   = wid >> 1, wc = wid & 1;     // warp 4x2 grid
    const int m0   = blockIdx.x * 128;

    const int r  = tid >> 1;
    const int kh = (tid & 1) * 16;
    const int grow = m0 + r;
    const bool valid = grow < M;

    float acc[2][8][4];
    #pragma unroll
    for (int mt = 0; mt < 2; ++mt)
        #pragma unroll
        for (int nt = 0; nt < 8; ++nt)
            #pragma unroll
            for (int j = 0; j < 4; ++j) acc[mt][nt][j] = 0.f;

    const uint32_t aAh = smem_addr_u32(sAh);
    const uint32_t aAl = smem_addr_u32(sAl);
    const uint32_t aBh = smem_addr_u32(sBh);
    const int a_row = wr * 32 + (lane & 15);
    const int a_kof = (lane >> 4) * 8;
    const int b_row = wc * 64 + (lane & 7) + ((lane >> 4) << 3);
    const int b_kof = ((lane >> 3) & 1) * 8;

    const int nkt = K >> 5;
    for (int kt = 0; kt < nkt; ++kt) {
        __syncthreads();
        // ---- fill A ----
        if (MODE == 0) {
            const float* ap = (const float*)A_ + (size_t)grow * K + kt * 32 + kh;
            float4 f0, f1, f2, f3;
            if (valid) {
                f0 = *(const float4*)(ap + 0);
                f1 = *(const float4*)(ap + 4);
                f2 = *(const float4*)(ap + 8);
                f3 = *(const float4*)(ap + 12);
            } else {
                f0 = make_float4(0.f, 0.f, 0.f, 0.f);
                f1 = f0; f2 = f0; f3 = f0;
            }
            uint4 uh0, uh1, ul0, ul1;
            uh0.x = pack_bf2(f0.x, f0.y); uh0.y = pack_bf2(f0.z, f0.w);
            uh0.z = pack_bf2(f1.x, f1.y); uh0.w = pack_bf2(f1.z, f1.w);
            uh1.x = pack_bf2(f2.x, f2.y); uh1.y = pack_bf2(f2.z, f2.w);
            uh1.z = pack_bf2(f3.x, f3.y); uh1.w = pack_bf2(f3.z, f3.w);
            const __nv_bfloat162* hp0 = (const __nv_bfloat162*)&uh0;
            const __nv_bfloat162* hp1 = (const __nv_bfloat162*)&uh1;
            float2 h;
            h = __bfloat1622float2(hp0[0]); ul0.x = pack_bf2(f0.x - h.x, f0.y - h.y);
            h = __bfloat1622float2(hp0[1]); ul0.y = pack_bf2(f0.z - h.x, f0.w - h.y);
            h = __bfloat1622float2(hp0[2]); ul0.z = pack_bf2(f1.x - h.x, f1.y - h.y);
            h = __bfloat1622float2(hp0[3]); ul0.w = pack_bf2(f1.z - h.x, f1.w - h.y);
            h = __bfloat1622float2(hp1[0]); ul1.x = pack_bf2(f2.x - h.x, f2.y - h.y);
            h = __bfloat1622float2(hp1[1]); ul1.y = pack_bf2(f2.z - h.x, f2.w - h.y);
            h = __bfloat1622float2(hp1[2]); ul1.z = pack_bf2(f3.x - h.x, f3.y - h.y);
            h = __bfloat1622float2(hp1[3]); ul1.w = pack_bf2(f3.z - h.x, f3.w - h.y);
            *(uint4*)&sAh[r * ASTRIDE + kh]     = uh0;
            *(uint4*)&sAh[r * ASTRIDE + kh + 8] = uh1;
            *(uint4*)&sAl[r * ASTRIDE + kh]     = ul0;
            *(uint4*)&sAl[r * ASTRIDE + kh + 8] = ul1;
        } else {
            const uint4 z = make_uint4(0u, 0u, 0u, 0u);
            const __nv_bfloat16* ah = (const __nv_bfloat16*)A_ + (size_t)grow * K + kt * 32 + kh;
            const __nv_bfloat16* al = Alo_ + (size_t)grow * K + kt * 32 + kh;
            uint4 h0 = valid ? *(const uint4*)(ah)     : z;
            uint4 h1 = valid ? *(const uint4*)(ah + 8) : z;
            uint4 l0 = valid ? *(const uint4*)(al)     : z;
            uint4 l1 = valid ? *(const uint4*)(al + 8) : z;
            *(uint4*)&sAh[r * ASTRIDE + kh]     = h0;
            *(uint4*)&sAh[r * ASTRIDE + kh + 8] = h1;
            *(uint4*)&sAl[r * ASTRIDE + kh]     = l0;
            *(uint4*)&sAl[r * ASTRIDE + kh + 8] = l1;
        }
        // ---- fill B (bf16, K-major) ----
        {
            const __nv_bfloat16* bh = Bhi + (size_t)r * K + kt * 32 + kh;
            *(uint4*)&sBh[r * ASTRIDE + kh]     = *(const uint4*)(bh + 0);
            *(uint4*)&sBh[r * ASTRIDE + kh + 8] = *(const uint4*)(bh + 8);
        }
        __syncthreads();

        #pragma unroll
        for (int ks = 0; ks < 2; ++ks) {
            const uint32_t aoff = (uint32_t)((a_row * ASTRIDE + ks * 16 + a_kof) * 2);
            const uint32_t boff = (uint32_t)((b_row * ASTRIDE + ks * 16 + b_kof) * 2);
            uint32_t ah[2][4], al[2][4], bb[8][2];
            ldsm_x4(ah[0], aAh + aoff);
            ldsm_x4(ah[1], aAh + aoff + 16 * ASTRIDE * 2);
            ldsm_x4(al[0], aAl + aoff);
            ldsm_x4(al[1], aAl + aoff + 16 * ASTRIDE * 2);
            #pragma unroll
            for (int p = 0; p < 4; ++p)
                ldsm_x4(&bb[p * 2][0], aBh + boff + (uint32_t)(p * 16 * ASTRIDE * 2));
            #pragma unroll
            for (int mt = 0; mt < 2; ++mt)
                #pragma unroll
                for (int nt = 0; nt < 8; ++nt) {
                    mma_bf16(acc[mt][nt], ah[mt], bb[nt]);
                    mma_bf16(acc[mt][nt], al[mt], bb[nt]);
                }
        }
    }

    // ---- epilogue ----
    const int colb = wc * 64 + (lane & 3) * 2;
    const int rowb = m0 + wr * 32 + (lane >> 2);
    #pragma unroll
    for (int mt = 0; mt < 2; ++mt) {
        #pragma unroll
        for (int nt = 0; nt < 8; ++nt) {
            int col = colb + nt * 8;
            float2 v0, v1;
            v0.x = acc[mt][nt][0]; v0.y = acc[mt][nt][1];
            v1.x = acc[mt][nt][2]; v1.y = acc[mt][nt][3];
            int row0 = rowb + mt * 16;
            int row1 = row0 + 8;
            if (MODE == 0) {
                float bx = __ldg(&bias[col]), by = __ldg(&bias[col + 1]);
                v0.x = fmaxf(v0.x + bx, 0.f); v0.y = fmaxf(v0.y + by, 0.f);
                v1.x = fmaxf(v1.x + bx, 0.f); v1.y = fmaxf(v1.y + by, 0.f);
                acc[mt][nt][0] = v0.x; acc[mt][nt][1] = v0.y;
                acc[mt][nt][2] = v1.x; acc[mt][nt][3] = v1.y;
                if (row0 < M) {
                    *(float2*)&C[(size_t)row0 * 128 + col] = v0;
                    uint32_t hh = pack_bf2(v0.x, v0.y);
                    float2 f = __bfloat1622float2(*(__nv_bfloat162*)&hh);
                    uint32_t ll = pack_bf2(v0.x - f.x, v0.y - f.y);
                    *(uint32_t*)&Chi[(size_t)row0 * 128 + col] = hh;
                    *(uint32_t*)&Clo[(size_t)row0 * 128 + col] = ll;
                }
                if (row1 < M) {
                    *(float2*)&C[(size_t)row1 * 128 + col] = v1;
                    uint32_t hh = pack_bf2(v1.x, v1.y);
                    float2 f = __bfloat1622float2(*(__nv_bfloat162*)&hh);
                    uint32_t ll = pack_bf2(v1.x - f.x, v1.y - f.y);
                    *(uint32_t*)&Chi[(size_t)row1 * 128 + col] = hh;
                    *(uint32_t*)&Clo[(size_t)row1 * 128 + col] = ll;
                }
            } else {
                if (row0 < M)
                    *(__half2*)&Cxh[(size_t)row0 * 128 + col] = __floats2half2_rn(v0.x, v0.y);
                if (row1 < M)
                    *(__half2*)&Cxh[(size_t)row1 * 128 + col] = __floats2half2_rn(v1.x, v1.y);
            }
        }
    }

    if (MODE == 1) {
        // ---- fused attention logits (att vectors hoisted) ----
        float as_r[4][2][2], ad_r[4][2][2];   // [hl][jb][ntb]
        #pragma unroll
        for (int hl = 0; hl < 4; ++hl)
            #pragma unroll
            for (int jb = 0; jb < 2; ++jb)
                #pragma unroll
                for (int ntb = 0; ntb < 2; ++ntb) {
                    int cmod = (lane & 3) * 2 + jb + 8 * ntb;
                    as_r[hl][jb][ntb] = __ldg(&att_s[(wc * 4 + hl) * 16 + cmod]);
                    ad_r[hl][jb][ntb] = __ldg(&att_d[(wc * 4 + hl) * 16 + cmod]);
                }
        #pragma unroll
        for (int mt = 0; mt < 2; ++mt) {
            float ss[2][4], dd[2][4];
            #pragma unroll
            for (int a = 0; a < 2; ++a)
                #pragma unroll
                for (int b = 0; b < 4; ++b) { ss[a][b] = 0.f; dd[a][b] = 0.f; }
            #pragma unroll
            for (int nt = 0; nt < 8; ++nt) {
                int hl = nt >> 1, ntb = nt & 1;
                #pragma unroll
                for (int j = 0; j < 4; ++j) {
                    int jb = j & 1, rj = j >> 1;
                    ss[rj][hl] = fmaf(acc[mt][nt][j], as_r[hl][jb][ntb], ss[rj][hl]);
                    dd[rj][hl] = fmaf(acc[mt][nt][j], ad_r[hl][jb][ntb], dd[rj][hl]);
                }
            }
            #pragma unroll
            for (int rj = 0; rj < 2; ++rj)
                #pragma unroll
                for (int hl = 0; hl < 4; ++hl) {
                    ss[rj][hl] += __shfl_xor_sync(0xffffffffu, ss[rj][hl], 1);
                    ss[rj][hl] += __shfl_xor_sync(0xffffffffu, ss[rj][hl], 2);
                    dd[rj][hl] += __shfl_xor_sync(0xffffffffu, dd[rj][hl], 1);
                    dd[rj][hl] += __shfl_xor_sync(0xffffffffu, dd[rj][hl], 2);
                }
            if ((lane & 3) == 0) {
                #pragma unroll
                for (int rj = 0; rj < 2; ++rj) {
                    int row = rowb + mt * 16 + rj * 8;
                    if (row < M) {
                        #pragma unroll
                        for (int hl = 0; hl < 4; ++hl) {
                            g_als[row * 8 + wc * 4 + hl] = ss[rj][hl];
                            g_ald[row * 8 + wc * 4 + hl] = dd[rj][hl];
                        }
                    }
                }
            }
        }
    }
}

// ================= classifier hidden layer via HMMA =================
#define CSTRIDE 40
__global__ __launch_bounds__(256, 2)
void cls_hid_gemm(const __nv_bfloat16* __restrict__ Ahi, const __nv_bfloat16* __restrict__ Alo,
                  const __nv_bfloat16* __restrict__ Bh, const float* __restrict__ b1,
                  float* __restrict__ Hid, int M)
{
    __shared__ __align__(16) __nv_bfloat16 sAh[128 * CSTRIDE];
    __shared__ __align__(16) __nv_bfloat16 sAl[128 * CSTRIDE];
    __shared__ __align__(16) __nv_bfloat16 sB[64 * CSTRIDE];

    const int tid = threadIdx.x;
    const int wid = tid >> 5, lane = tid & 31;
    const int wr = wid >> 1, wc = wid & 1;
    const int m0 = blockIdx.x * 128;
    const int r = tid >> 1;
    const int kh = (tid & 1) * 16;
    const int grow = m0 + r;
    const bool valid = grow < M;

    float acc[2][4][4];
    #pragma unroll
    for (int mt = 0; mt < 2; ++mt)
        #pragma unroll
        for (int nt = 0; nt < 4; ++nt)
            #pragma unroll
            for (int j = 0; j < 4; ++j) acc[mt][nt][j] = 0.f;

    const uint32_t aAh = smem_addr_u32(sAh);
    const uint32_t aAl = smem_addr_u32(sAl);
    const uint32_t aB  = smem_addr_u32(sB);
    const int a_row = wr * 32 + (lane & 15);
    const int a_kof = (lane >> 4) * 8;
    const int b_row = wc * 32 + (lane & 7) + ((lane >> 4) << 3);
    const int b_kof = ((lane >> 3) & 1) * 8;

    #pragma unroll
    for (int kt = 0; kt < 4; ++kt) {
        __syncthreads();
        {
            const uint4 z = make_uint4(0u, 0u, 0u, 0u);
            const __nv_bfloat16* ah = Ahi + (size_t)grow * HID + kt * 32 + kh;
            const __nv_bfloat16* al = Alo + (size_t)grow * HID + kt * 32 + kh;
            uint4 h0 = valid ? *(const uint4*)(ah)     : z;
            uint4 h1 = valid ? *(const uint4*)(ah + 8) : z;
            uint4 l0 = valid ? *(const uint4*)(al)     : z;
            uint4 l1 = valid ? *(const uint4*)(al + 8) : z;
            *(uint4*)&sAh[r * CSTRIDE + kh]     = h0;
            *(uint4*)&sAh[r * CSTRIDE + kh + 8] = h1;
            *(uint4*)&sAl[r * CSTRIDE + kh]     = l0;
            *(uint4*)&sAl[r * CSTRIDE + kh + 8] = l1;
        }
        if (tid < 128) {
            int br = tid >> 1;
            const __nv_bfloat16* bp = Bh + (size_t)br * HID + kt * 32 + kh;
            *(uint4*)&sB[br * CSTRIDE + kh]     = *(const uint4*)(bp + 0);
            *(uint4*)&sB[br * CSTRIDE + kh + 8] = *(const uint4*)(bp + 8);
        }
        __syncthreads();

        #pragma unroll
        for (int ks = 0; ks < 2; ++ks) {
            const uint32_t aoff = (uint32_t)((a_row * CSTRIDE + ks * 16 + a_kof) * 2);
            const uint32_t boff = (uint32_t)((b_row * CSTRIDE + ks * 16 + b_kof) * 2);
            uint32_t ah[2][4], al[2][4], bb[4][2];
            ldsm_x4(ah[0], aAh + aoff);
            ldsm_x4(ah[1], aAh + aoff + 16 * CSTRIDE * 2);
            ldsm_x4(al[0], aAl + aoff);
            ldsm_x4(al[1], aAl + aoff + 16 * CSTRIDE * 2);
            ldsm_x4(&bb[0][0], aB + boff);
            ldsm_x4(&bb[2][0], aB + boff + (uint32_t)(16 * CSTRIDE * 2));
            #pragma unroll
            for (int mt = 0; mt < 2; ++mt)
                #pragma unroll
                for (int nt = 0; nt < 4; ++nt) {
                    mma_bf16(acc[mt][nt], ah[mt], bb[nt]);
                    mma_bf16(acc[mt][nt], al[mt], bb[nt]);
                }
        }
    }

    const int colb = wc * 32 + (lane & 3) * 2;
    const int rowb = m0 + wr * 32 + (lane >> 2);
    #pragma unroll
    for (int mt = 0; mt < 2; ++mt) {
        #pragma unroll
        for (int nt = 0; nt < 4; ++nt) {
            int col = colb + nt * 8;
            float bx = __ldg(&b1[col]), by = __ldg(&b1[col + 1]);
            float2 v0, v1;
            v0.x = fmaxf(acc[mt][nt][0] + bx, 0.f);
            v0.y = fmaxf(acc[mt][nt][1] + by, 0.f);
            v1.x = fmaxf(acc[mt][nt][2] + bx, 0.f);
            v1.y = fmaxf(acc[mt][nt][3] + by, 0.f);
            int row0 = rowb + mt * 16;
            int row1 = row0 + 8;
            if (row0 < M) *(float2*)&Hid[(size_t)row0 * 64 + col] = v0;
            if (row1 < M) *(float2*)&Hid[(size_t)row1 * 64 + col] = v1;
        }
    }
}

// ================= logits + log_softmax (warp per row) =================
__global__ __launch_bounds__(256)
void logits_kernel(const float* __restrict__ hid,
                   const float* __restrict__ w2, const float* __restrict__ b2,
                   float* __restrict__ out)
{
    __shared__ float s_w2[64 * OUT_DIM];
    __shared__ float s_b2[OUT_DIM];
    __shared__ float s_hid[8][64];

    int tid = threadIdx.x;
    for (int i = tid; i < 64 * OUT_DIM; i += 256) s_w2[i] = w2[i];
    if (tid < OUT_DIM) s_b2[tid] = b2[tid];
    __syncthreads();

    int warp = tid >> 5, lane = tid & 31;
    int stride = gridDim.x * 8;
    for (int row = blockIdx.x * 8 + warp; row < N_NODES; row += stride) {
        float2 hv = *(const float2*)&hid[(size_t)row * 64 + lane * 2];
        *(float2*)&s_hid[warp][lane * 2] = hv;
        __syncwarp();
        int o = lane & 15;
        int kbase = (lane >> 4) * 32;
        float part = 0.f;
        #pragma unroll 8
        for (int k = 0; k < 32; ++k)
            part = fmaf(s_hid[warp][kbase + k], s_w2[(kbase + k) * OUT_DIM + o], part);
        part += __shfl_xor_sync(0xffffffffu, part, 16);
        float logit = part + s_b2[o];
        float mx = logit;
        #pragma unroll
        for (int off = 8; off; off >>= 1)
            mx = fmaxf(mx, __shfl_xor_sync(0xffffffffu, mx, off));
        float ex = __expf(logit - mx);
        float sm = ex;
        #pragma unroll
        for (int off = 8; off; off >>= 1)
            sm += __shfl_xor_sync(0xffffffffu, sm, off);
        float res = logit - mx - logf(sm);
        if (lane < 16) out[(size_t)row * OUT_DIM + lane] = res;
        __syncwarp();
    }
}

// ================= GAT aggregation (warp per dst, fp16 xh) =================
__global__ __launch_bounds__(256)
void gat_aggregate(const __half* __restrict__ xh,
                   const float* __restrict__ gat_b,
                   const float* __restrict__ ln_g,
                   const float* __restrict__ ln_b,
                   float* __restrict__ h,
                   __nv_bfloat16* __restrict__ hhi,
                   __nv_bfloat16* __restrict__ hlo)
{
    int w = (blockIdx.x * blockDim.x + threadIdx.x) >> 5;
    if (w >= N_NODES) return;
    int lane = threadIdx.x & 31;
    int hd = lane >> 2;
    int f = lane * 4;

    float a_d = g_ald[w * NHEAD + hd];
    float e0 = g_als[w * NHEAD + hd] + a_d;
    e0 = fmaxf(e0, 0.2f * e0);
    float m = e0;
    float denom = 1.0f;
    float4 acc;
    {
        uint2 u = *(const uint2*)&xh[(size_t)w * HID + f];
        const __half2* hp = (const __half2*)&u;
        float2 a = __half22float2(hp[0]);
        float2 b = __half22float2(hp[1]);
        acc.x = a.x; acc.y = a.y; acc.z = b.x; acc.w = b.y;
    }

    int beg = g_rowptr[w], end = g_rowptr[w + 1];
    for (int i = beg; i < end; ++i) {
        int s = g_col[i];
        float e2 = g_als[s * NHEAD + hd] + a_d;
        e2 = fmaxf(e2, 0.2f * e2);
        float mn = fmaxf(m, e2);
        float sc = __expf(m - mn);
        float p  = __expf(e2 - mn);
        uint2 u = *(const uint2*)&xh[(size_t)s * HID + f];
        const __half2* hp = (const __half2*)&u;
        float2 va = __half22float2(hp[0]);
        float2 vb = __half22float2(hp[1]);
        acc.x = acc.x * sc + p * va.x;
        acc.y = acc.y * sc + p * va.y;
        acc.z = acc.z * sc + p * vb.x;
        acc.w = acc.w * sc + p * vb.y;
        denom = denom * sc + p;
        m = mn;
    }

    float inv = 1.0f / denom;
    float4 r  = *(const float4*)&h[(size_t)w * HID + f];
    float4 gb = *(const float4*)&gat_b[f];
    float v0 = fmaf(acc.x, inv, gb.x + r.x);
    float v1 = fmaf(acc.y, inv, gb.y + r.y);
    float v2 = fmaf(acc.z, inv, gb.z + r.z);
    float v3 = fmaf(acc.w, inv, gb.w + r.w);

    float sum = v0 + v1 + v2 + v3;
    float sq  = v0 * v0 + v1 * v1 + v2 * v2 + v3 * v3;
    #pragma unroll
    for (int off = 16; off; off >>= 1) {
        sum += __shfl_xor_sync(0xffffffffu, sum, off);
        sq  += __shfl_xor_sync(0xffffffffu, sq,  off);
    }
    float mean = sum * (1.0f / 128.0f);
    float var  = sq  * (1.0f / 128.0f) - mean * mean;
    float rs = rsqrtf(var + 1e-5f);

    float4 g4 = *(const float4*)&ln_g[f];
    float4 b4 = *(const float4*)&ln_b[f];
    float4 o;
    o.x = fmaxf((v0 - mean) * rs * g4.x + b4.x, 0.f);
    o.y = fmaxf((v1 - mean) * rs * g4.y + b4.y, 0.f);
    o.z = fmaxf((v2 - mean) * rs * g4.z + b4.z, 0.f);
    o.w = fmaxf((v3 - mean) * rs * g4.w + b4.w, 0.f);
    *(float4*)&h[(size_t)w * HID + f] = o;

    uint32_t h0 = pack_bf2(o.x, o.y), h1 = pack_bf2(o.z, o.w);
    float2 f0 = __bfloat1622float2(*(__nv_bfloat162*)&h0);
    float2 f1 = __bfloat1622float2(*(__nv_bfloat162*)&h1);
    uint32_t l0 = pack_bf2(o.x - f0.x, o.y - f0.y);
    uint32_t l1 = pack_bf2(o.z - f1.x, o.w - f1.y);
    uint2 uh; uh.x = h0; uh.y = h1;
    uint2 ul; ul.x = l0; ul.y = l1;
    *(uint2*)&hhi[(size_t)w * HID + f] = uh;
    *(uint2*)&hlo[(size_t)w * HID + f] = ul;
}

// ================= launch =================
extern "C" void kernel_launch(void* const* d_in, const int* in_sizes, int n_in,
                              void* d_out, int out_size)
{
    const float* x       = (const float*)d_in[0];
    const int*   ei      = (const int*)  d_in[1];
    const float* proj_w  = (const float*)d_in[2];
    const float* proj_b  = (const float*)d_in[3];
    const float* lin_w   = (const float*)d_in[4];
    const float* att_src = (const float*)d_in[5];
    const float* att_dst = (const float*)d_in[6];
    const float* gat_b   = (const float*)d_in[7];
    const float* ln_g    = (const float*)d_in[8];
    const float* ln_b    = (const float*)d_in[9];
    const float* cls_w1  = (const float*)d_in[10];
    const float* cls_b1  = (const float*)d_in[11];
    const float* cls_w2  = (const float*)d_in[12];
    const float* cls_b2  = (const float*)d_in[13];
    float* out = (float*)d_out;

    const int* src = ei;
    const int* dst = ei + N_EDGES;

    float *h_ptr = nullptr, *hid_ptr = nullptr;
    __half* xhh_ptr = nullptr;
    __nv_bfloat16 *bhi = nullptr, *hhi = nullptr, *hlo = nullptr;
    cudaGetSymbolAddress((void**)&h_ptr, g_h);
    cudaGetSymbolAddress((void**)&xhh_ptr, g_xhh);
    cudaGetSymbolAddress((void**)&hid_ptr, g_hid);
    cudaGetSymbolAddress((void**)&bhi, g_bhi);
    cudaGetSymbolAddress((void**)&hhi, g_hhi);
    cudaGetSymbolAddress((void**)&hlo, g_hlo);

    const int GEMM_GRID = (N_NODES + 127) / 128;  // 391
    const int SCAN_BLOCKS = (N_NODES + 1 + 1023) / 1024;  // 49

    // my#1-3: conversions + independent CSR prefix
    conv_all_kernel<<<128, 256>>>(proj_w, lin_w, cls_w1);
    zero_rowptr_kernel<<<(N_NODES + 1 + 255) / 256, 256>>>();
    hist_kernel<<<(N_EDGES + 255) / 256, 256>>>(dst);

    // my#4 (ncu-profiled): projection GEMM  h = relu(x @ proj_w + b)
    gemm_mma<0><<<GEMM_GRID, 256>>>(
        x, nullptr, bhi + B_PROJ_OFF, proj_b,
        nullptr, nullptr, h_ptr, nullptr, hhi, hlo, N_NODES, IN_DIM);

    // layer-0 GEMM + fused attention logits (fp16 xh out)
    gemm_mma<1><<<GEMM_GRID, 256>>>(
        hhi, hlo, bhi + B_LIN_OFF, nullptr,
        att_src, att_dst, nullptr, xhh_ptr, nullptr, nullptr, N_NODES, HID);

    // CSR build tail
    scan_block_kernel<<<SCAN_BLOCKS, 1024>>>();
    scan_sums_kernel<<<1, 64>>>(SCAN_BLOCKS);
    scan_add_kernel<<<SCAN_BLOCKS, 1024>>>();
    scatter_kernel<<<(N_EDGES + 255) / 256, 256>>>(src, dst);

    // layer 0 aggregation
    gat_aggregate<<<N_NODES / 8, 256>>>(
        xhh_ptr, gat_b, ln_g, ln_b, h_ptr, hhi, hlo);

    // layers 1..2
    for (int l = 1; l < NLAYER; ++l) {
        gemm_mma<1><<<GEMM_GRID, 256>>>(
            hhi, hlo, bhi + B_LIN_OFF + l * 128 * HID,
            nullptr, att_src + l * NHEAD * CH, att_dst + l * NHEAD * CH,
            nullptr, xhh_ptr, nullptr, nullptr, N_NODES, HID);
        gat_aggregate<<<N_NODES / 8, 256>>>(
            xhh_ptr, gat_b + l * HID, ln_g + l * HID, ln_b + l * HID, h_ptr, hhi, hlo);
    }

    // classifier: hidden layer on tensor cores, then tiny logits+log_softmax
    cls_hid_gemm<<<GEMM_GRID, 256>>>(hhi, hlo, bhi + B_CLS_OFF, cls_b1, hid_ptr, N_NODES);
    logits_kernel<<<592, 256>>>(hid_ptr, cls_w2, cls_b2, out);
}

// round 16
// speedup vs baseline: 1.2243x; 1.1345x over previous
#include <cuda_runtime.h>
#include <cuda_bf16.h>
#include <cuda_fp16.h>
#include <math.h>
#include <stdint.h>

#define N_NODES 50000
#define N_EDGES 500000
#define IN_DIM  384
#define HID     128
#define NHEAD   8
#define CH      16
#define NLAYER  3
#define OUT_DIM 16

// ================= device scratch =================
__device__ int   g_rowptr[N_NODES + 1];
__device__ int   g_cursor[N_NODES];
__device__ int   g_col[N_EDGES];
__device__ int   g_bsums[64];
__device__ float g_h[(size_t)N_NODES * HID];
__device__ __half g_xhh[(size_t)N_NODES * HID];   // fp16 xh (GEMM out, aggregate in)
__device__ float g_als[N_NODES * NHEAD];
__device__ float g_ald[N_NODES * NHEAD];
__device__ float g_hid[(size_t)N_NODES * 64];
__device__ __nv_bfloat16 g_hhi[(size_t)N_NODES * HID];
__device__ __nv_bfloat16 g_hlo[(size_t)N_NODES * HID];   // used by proj A-split path only
// bf16 weights (hi only), K-major
#define B_PROJ_OFF 0
#define B_LIN_OFF  (128 * IN_DIM)
#define B_CLS_OFF  (B_LIN_OFF + NLAYER * 128 * HID)
__device__ __nv_bfloat16 g_bhi[128 * IN_DIM + NLAYER * 128 * HID + 64 * HID];

// ================= CSR build =================
__global__ void zero_rowptr_kernel() {
    int i = blockIdx.x * blockDim.x + threadIdx.x;
    if (i <= N_NODES) g_rowptr[i] = 0;
}
__global__ void hist_kernel(const int* __restrict__ dst) {
    int i = blockIdx.x * blockDim.x + threadIdx.x;
    if (i < N_EDGES) atomicAdd(&g_rowptr[dst[i] + 1], 1);
}
__global__ void scan_block_kernel() {
    __shared__ int s[1024];
    const int n = N_NODES + 1;
    int t = threadIdx.x;
    int gid = blockIdx.x * 1024 + t;
    s[t] = (gid < n) ? g_rowptr[gid] : 0;
    __syncthreads();
    #pragma unroll
    for (int off = 1; off < 1024; off <<= 1) {
        int v = (t >= off) ? s[t - off] : 0;
        __syncthreads();
        s[t] += v;
        __syncthreads();
    }
    if (gid < n) g_rowptr[gid] = s[t];
    if (t == 1023) g_bsums[blockIdx.x] = s[1023];
}
__global__ void scan_sums_kernel(int nb) {
    __shared__ int ws[2];
    int t = threadIdx.x;
    int lane = t & 31, w = t >> 5;
    int v = (t < nb) ? g_bsums[t] : 0;
    int x = v;
    #pragma unroll
    for (int off = 1; off < 32; off <<= 1) {
        int y = __shfl_up_sync(0xffffffffu, x, off);
        if (lane >= off) x += y;
    }
    if (lane == 31) ws[w] = x;
    __syncthreads();
    if (w == 1) x += ws[0];
    if (t < nb) g_bsums[t] = x - v;   // exclusive
}
__global__ void scan_add_kernel() {
    const int n = N_NODES + 1;
    int gid = blockIdx.x * 1024 + threadIdx.x;
    if (gid < n) {
        int v = g_rowptr[gid] + g_bsums[blockIdx.x];
        g_rowptr[gid] = v;
        if (gid < N_NODES) g_cursor[gid] = v;
    }
}
__global__ void scatter_kernel(const int* __restrict__ src, const int* __restrict__ dst) {
    int i = blockIdx.x * blockDim.x + threadIdx.x;
    if (i < N_EDGES) {
        int d = dst[i];
        int pos = atomicAdd(&g_cursor[d], 1);
        g_col[pos] = src[i];
    }
}

// ================= helpers =================
__device__ __forceinline__ uint32_t pack_bf2(float x, float y) {
    __nv_bfloat162 t = __floats2bfloat162_rn(x, y);
    return *reinterpret_cast<uint32_t*>(&t);
}

// ONE launch converts all weights (hi only): proj, lin[3], cls_w1
__global__ void conv_all_kernel(const float* __restrict__ proj_w,
                                const float* __restrict__ lin_w,
                                const float* __restrict__ cls_w1) {
    const int T1 = IN_DIM * 128;
    const int T2 = T1 + NLAYER * HID * 128;
    const int TOT = T2 + HID * 64;
    for (int i = blockIdx.x * blockDim.x + threadIdx.x; i < TOT; i += gridDim.x * blockDim.x) {
        if (i < T1) {
            int k = i >> 7, n = i & 127;
            float v = proj_w[(size_t)k * 128 + n];
            g_bhi[B_PROJ_OFF + (size_t)n * IN_DIM + k] = __float2bfloat16(v);
        } else if (i < T2) {
            int j = i - T1;
            int l = j / (HID * 128);
            j -= l * HID * 128;
            int k = j >> 7, n = j & 127;
            float v = lin_w[(size_t)l * HID * HID + (size_t)k * 128 + n];
            g_bhi[B_LIN_OFF + l * 128 * HID + (size_t)n * HID + k] = __float2bfloat16(v);
        } else {
            int j = i - T2;              // w1 [128][64]
            int k = j >> 6, n = j & 63;
            float v = cls_w1[(size_t)k * 64 + n];
            g_bhi[B_CLS_OFF + (size_t)n * HID + k] = __float2bfloat16(v);
        }
    }
}

// ================= HMMA GEMM, R10 config ==========
// C[M,128] = A[M,K] @ W.  Block 128x128, 8 warps 4(m)x2(n), K-tile 32.
// MODE 0 (proj):  2-term A split (Ah*B + Al*B); out fp32 C + bf16 hi split.
// MODE 1 (layer): 1-term bf16 A; out fp16 Cxh + fused attn logits.
#define ASTRIDE 40   // bf16 elems per smem row (pad -> conflict-free)

__device__ __forceinline__ uint32_t smem_addr_u32(const void* p) {
    return (uint32_t)__cvta_generic_to_shared(p);
}
__device__ __forceinline__ void ldsm_x4(uint32_t* r, uint32_t addr) {
    asm volatile("ldmatrix.sync.aligned.m8n8.x4.shared.b16 {%0,%1,%2,%3}, [%4];"
                 : "=r"(r[0]), "=r"(r[1]), "=r"(r[2]), "=r"(r[3]) : "r"(addr));
}
__device__ __forceinline__ void mma_bf16(float* d, const uint32_t* a, const uint32_t* b) {
    asm volatile(
        "mma.sync.aligned.m16n8k16.row.col.f32.bf16.bf16.f32 "
        "{%0,%1,%2,%3}, {%4,%5,%6,%7}, {%8,%9}, {%0,%1,%2,%3};"
        : "+f"(d[0]), "+f"(d[1]), "+f"(d[2]), "+f"(d[3])
        : "r"(a[0]), "r"(a[1]), "r"(a[2]), "r"(a[3]), "r"(b[0]), "r"(b[1]));
}

template<int MODE>
__global__ __launch_bounds__(256, 2)
void gemm_mma(const void* __restrict__ A_, const __nv_bfloat16* __restrict__ Alo_,
              const __nv_bfloat16* __restrict__ Bhi,
              const float* __restrict__ bias,
              const float* __restrict__ att_s, const float* __restrict__ att_d,
              float* __restrict__ C, __half* __restrict__ Cxh,
              __nv_bfloat16* __restrict__ Chi, __nv_bfloat16* __restrict__ Clo,
              int M, int K)
{
    __shared__ __align__(16) __nv_bfloat16 sAh[128 * ASTRIDE];
    __shared__ __align__(16) __nv_bfloat16 sAl[(MODE == 0) ? 128 * ASTRIDE : 1];
    __shared__ __align__(16) __nv_bfloat16 sBh[128 * ASTRIDE];

    const int tid  = threadIdx.x;
    const int wid  = tid >> 5, lane = tid & 31;
    const int wr   = wid >> 1, wc = wid & 1;     // warp 4x2 grid
    const int m0   = blockIdx.x * 128;

    const int r  = tid >> 1;
    const int kh = (tid & 1) * 16;
    const int grow = m0 + r;
    const bool valid = grow < M;

    float acc[2][8][4];
    #pragma unroll
    for (int mt = 0; mt < 2; ++mt)
        #pragma unroll
        for (int nt = 0; nt < 8; ++nt)
            #pragma unroll
            for (int j = 0; j < 4; ++j) acc[mt][nt][j] = 0.f;

    const uint32_t aAh = smem_addr_u32(sAh);
    const uint32_t aAl = smem_addr_u32(sAl);
    const uint32_t aBh = smem_addr_u32(sBh);
    const int a_row = wr * 32 + (lane & 15);
    const int a_kof = (lane >> 4) * 8;
    const int b_row = wc * 64 + (lane & 7) + ((lane >> 4) << 3);
    const int b_kof = ((lane >> 3) & 1) * 8;

    const int nkt = K >> 5;
    for (int kt = 0; kt < nkt; ++kt) {
        __syncthreads();
        // ---- fill A ----
        if (MODE == 0) {
            const float* ap = (const float*)A_ + (size_t)grow * K + kt * 32 + kh;
            float4 f0, f1, f2, f3;
            if (valid) {
                f0 = *(const float4*)(ap + 0);
                f1 = *(const float4*)(ap + 4);
                f2 = *(const float4*)(ap + 8);
                f3 = *(const float4*)(ap + 12);
            } else {
                f0 = make_float4(0.f, 0.f, 0.f, 0.f);
                f1 = f0; f2 = f0; f3 = f0;
            }
            uint4 uh0, uh1, ul0, ul1;
            uh0.x = pack_bf2(f0.x, f0.y); uh0.y = pack_bf2(f0.z, f0.w);
            uh0.z = pack_bf2(f1.x, f1.y); uh0.w = pack_bf2(f1.z, f1.w);
            uh1.x = pack_bf2(f2.x, f2.y); uh1.y = pack_bf2(f2.z, f2.w);
            uh1.z = pack_bf2(f3.x, f3.y); uh1.w = pack_bf2(f3.z, f3.w);
            const __nv_bfloat162* hp0 = (const __nv_bfloat162*)&uh0;
            const __nv_bfloat162* hp1 = (const __nv_bfloat162*)&uh1;
            float2 h;
            h = __bfloat1622float2(hp0[0]); ul0.x = pack_bf2(f0.x - h.x, f0.y - h.y);
            h = __bfloat1622float2(hp0[1]); ul0.y = pack_bf2(f0.z - h.x, f0.w - h.y);
            h = __bfloat1622float2(hp0[2]); ul0.z = pack_bf2(f1.x - h.x, f1.y - h.y);
            h = __bfloat1622float2(hp0[3]); ul0.w = pack_bf2(f1.z - h.x, f1.w - h.y);
            h = __bfloat1622float2(hp1[0]); ul1.x = pack_bf2(f2.x - h.x, f2.y - h.y);
            h = __bfloat1622float2(hp1[1]); ul1.y = pack_bf2(f2.z - h.x, f2.w - h.y);
            h = __bfloat1622float2(hp1[2]); ul1.z = pack_bf2(f3.x - h.x, f3.y - h.y);
            h = __bfloat1622float2(hp1[3]); ul1.w = pack_bf2(f3.z - h.x, f3.w - h.y);
            *(uint4*)&sAh[r * ASTRIDE + kh]     = uh0;
            *(uint4*)&sAh[r * ASTRIDE + kh + 8] = uh1;
            *(uint4*)&sAl[r * ASTRIDE + kh]     = ul0;
            *(uint4*)&sAl[r * ASTRIDE + kh + 8] = ul1;
        } else {
            const uint4 z = make_uint4(0u, 0u, 0u, 0u);
            const __nv_bfloat16* ah = (const __nv_bfloat16*)A_ + (size_t)grow * K + kt * 32 + kh;
            uint4 h0 = valid ? *(const uint4*)(ah)     : z;
            uint4 h1 = valid ? *(const uint4*)(ah + 8) : z;
            *(uint4*)&sAh[r * ASTRIDE + kh]     = h0;
            *(uint4*)&sAh[r * ASTRIDE + kh + 8] = h1;
        }
        // ---- fill B (bf16, K-major) ----
        {
            const __nv_bfloat16* bh = Bhi + (size_t)r * K + kt * 32 + kh;
            *(uint4*)&sBh[r * ASTRIDE + kh]     = *(const uint4*)(bh + 0);
            *(uint4*)&sBh[r * ASTRIDE + kh + 8] = *(const uint4*)(bh + 8);
        }
        __syncthreads();

        #pragma unroll
        for (int ks = 0; ks < 2; ++ks) {
            const uint32_t aoff = (uint32_t)((a_row * ASTRIDE + ks * 16 + a_kof) * 2);
            const uint32_t boff = (uint32_t)((b_row * ASTRIDE + ks * 16 + b_kof) * 2);
            uint32_t ah[2][4], al[2][4], bb[8][2];
            ldsm_x4(ah[0], aAh + aoff);
            ldsm_x4(ah[1], aAh + aoff + 16 * ASTRIDE * 2);
            if (MODE == 0) {
                ldsm_x4(al[0], aAl + aoff);
                ldsm_x4(al[1], aAl + aoff + 16 * ASTRIDE * 2);
            }
            #pragma unroll
            for (int p = 0; p < 4; ++p)
                ldsm_x4(&bb[p * 2][0], aBh + boff + (uint32_t)(p * 16 * ASTRIDE * 2));
            #pragma unroll
            for (int mt = 0; mt < 2; ++mt)
                #pragma unroll
                for (int nt = 0; nt < 8; ++nt) {
                    mma_bf16(acc[mt][nt], ah[mt], bb[nt]);
                    if (MODE == 0) mma_bf16(acc[mt][nt], al[mt], bb[nt]);
                }
        }
    }

    // ---- epilogue ----
    const int colb = wc * 64 + (lane & 3) * 2;
    const int rowb = m0 + wr * 32 + (lane >> 2);
    #pragma unroll
    for (int mt = 0; mt < 2; ++mt) {
        #pragma unroll
        for (int nt = 0; nt < 8; ++nt) {
            int col = colb + nt * 8;
            float2 v0, v1;
            v0.x = acc[mt][nt][0]; v0.y = acc[mt][nt][1];
            v1.x = acc[mt][nt][2]; v1.y = acc[mt][nt][3];
            int row0 = rowb + mt * 16;
            int row1 = row0 + 8;
            if (MODE == 0) {
                float bx = __ldg(&bias[col]), by = __ldg(&bias[col + 1]);
                v0.x = fmaxf(v0.x + bx, 0.f); v0.y = fmaxf(v0.y + by, 0.f);
                v1.x = fmaxf(v1.x + bx, 0.f); v1.y = fmaxf(v1.y + by, 0.f);
                acc[mt][nt][0] = v0.x; acc[mt][nt][1] = v0.y;
                acc[mt][nt][2] = v1.x; acc[mt][nt][3] = v1.y;
                if (row0 < M) {
                    *(float2*)&C[(size_t)row0 * 128 + col] = v0;
                    *(uint32_t*)&Chi[(size_t)row0 * 128 + col] = pack_bf2(v0.x, v0.y);
                }
                if (row1 < M) {
                    *(float2*)&C[(size_t)row1 * 128 + col] = v1;
                    *(uint32_t*)&Chi[(size_t)row1 * 128 + col] = pack_bf2(v1.x, v1.y);
                }
            } else {
                if (row0 < M)
                    *(__half2*)&Cxh[(size_t)row0 * 128 + col] = __floats2half2_rn(v0.x, v0.y);
                if (row1 < M)
                    *(__half2*)&Cxh[(size_t)row1 * 128 + col] = __floats2half2_rn(v1.x, v1.y);
            }
        }
    }

    if (MODE == 1) {
        // ---- fused attention logits (att vectors hoisted) ----
        float as_r[4][2][2], ad_r[4][2][2];   // [hl][jb][ntb]
        #pragma unroll
        for (int hl = 0; hl < 4; ++hl)
            #pragma unroll
            for (int jb = 0; jb < 2; ++jb)
                #pragma unroll
                for (int ntb = 0; ntb < 2; ++ntb) {
                    int cmod = (lane & 3) * 2 + jb + 8 * ntb;
                    as_r[hl][jb][ntb] = __ldg(&att_s[(wc * 4 + hl) * 16 + cmod]);
                    ad_r[hl][jb][ntb] = __ldg(&att_d[(wc * 4 + hl) * 16 + cmod]);
                }
        #pragma unroll
        for (int mt = 0; mt < 2; ++mt) {
            float ss[2][4], dd[2][4];
            #pragma unroll
            for (int a = 0; a < 2; ++a)
                #pragma unroll
                for (int b = 0; b < 4; ++b) { ss[a][b] = 0.f; dd[a][b] = 0.f; }
            #pragma unroll
            for (int nt = 0; nt < 8; ++nt) {
                int hl = nt >> 1, ntb = nt & 1;
                #pragma unroll
                for (int j = 0; j < 4; ++j) {
                    int jb = j & 1, rj = j >> 1;
                    ss[rj][hl] = fmaf(acc[mt][nt][j], as_r[hl][jb][ntb], ss[rj][hl]);
                    dd[rj][hl] = fmaf(acc[mt][nt][j], ad_r[hl][jb][ntb], dd[rj][hl]);
                }
            }
            #pragma unroll
            for (int rj = 0; rj < 2; ++rj)
                #pragma unroll
                for (int hl = 0; hl < 4; ++hl) {
                    ss[rj][hl] += __shfl_xor_sync(0xffffffffu, ss[rj][hl], 1);
                    ss[rj][hl] += __shfl_xor_sync(0xffffffffu, ss[rj][hl], 2);
                    dd[rj][hl] += __shfl_xor_sync(0xffffffffu, dd[rj][hl], 1);
                    dd[rj][hl] += __shfl_xor_sync(0xffffffffu, dd[rj][hl], 2);
                }
            if ((lane & 3) == 0) {
                #pragma unroll
                for (int rj = 0; rj < 2; ++rj) {
                    int row = rowb + mt * 16 + rj * 8;
                    if (row < M) {
                        #pragma unroll
                        for (int hl = 0; hl < 4; ++hl) {
                            g_als[row * 8 + wc * 4 + hl] = ss[rj][hl];
                            g_ald[row * 8 + wc * 4 + hl] = dd[rj][hl];
                        }
                    }
                }
            }
        }
    }
}

// ================= classifier hidden layer via HMMA (1-term bf16) ======
#define CSTRIDE 40
__global__ __launch_bounds__(256, 2)
void cls_hid_gemm(const __nv_bfloat16* __restrict__ Ahi,
                  const __nv_bfloat16* __restrict__ Bh, const float* __restrict__ b1,
                  float* __restrict__ Hid, int M)
{
    __shared__ __align__(16) __nv_bfloat16 sAh[128 * CSTRIDE];
    __shared__ __align__(16) __nv_bfloat16 sB[64 * CSTRIDE];

    const int tid = threadIdx.x;
    const int wid = tid >> 5, lane = tid & 31;
    const int wr = wid >> 1, wc = wid & 1;
    const int m0 = blockIdx.x * 128;
    const int r = tid >> 1;
    const int kh = (tid & 1) * 16;
    const int grow = m0 + r;
    const bool valid = grow < M;

    float acc[2][4][4];
    #pragma unroll
    for (int mt = 0; mt < 2; ++mt)
        #pragma unroll
        for (int nt = 0; nt < 4; ++nt)
            #pragma unroll
            for (int j = 0; j < 4; ++j) acc[mt][nt][j] = 0.f;

    const uint32_t aAh = smem_addr_u32(sAh);
    const uint32_t aB  = smem_addr_u32(sB);
    const int a_row = wr * 32 + (lane & 15);
    const int a_kof = (lane >> 4) * 8;
    const int b_row = wc * 32 + (lane & 7) + ((lane >> 4) << 3);
    const int b_kof = ((lane >> 3) & 1) * 8;

    #pragma unroll
    for (int kt = 0; kt < 4; ++kt) {
        __syncthreads();
        {
            const uint4 z = make_uint4(0u, 0u, 0u, 0u);
            const __nv_bfloat16* ah = Ahi + (size_t)grow * HID + kt * 32 + kh;
            uint4 h0 = valid ? *(const uint4*)(ah)     : z;
            uint4 h1 = valid ? *(const uint4*)(ah + 8) : z;
            *(uint4*)&sAh[r * CSTRIDE + kh]     = h0;
            *(uint4*)&sAh[r * CSTRIDE + kh + 8] = h1;
        }
        if (tid < 128) {
            int br = tid >> 1;
            const __nv_bfloat16* bp = Bh + (size_t)br * HID + kt * 32 + kh;
            *(uint4*)&sB[br * CSTRIDE + kh]     = *(const uint4*)(bp + 0);
            *(uint4*)&sB[br * CSTRIDE + kh + 8] = *(const uint4*)(bp + 8);
        }
        __syncthreads();

        #pragma unroll
        for (int ks = 0; ks < 2; ++ks) {
            const uint32_t aoff = (uint32_t)((a_row * CSTRIDE + ks * 16 + a_kof) * 2);
            const uint32_t boff = (uint32_t)((b_row * CSTRIDE + ks * 16 + b_kof) * 2);
            uint32_t ah[2][4], bb[4][2];
            ldsm_x4(ah[0], aAh + aoff);
            ldsm_x4(ah[1], aAh + aoff + 16 * CSTRIDE * 2);
            ldsm_x4(&bb[0][0], aB + boff);
            ldsm_x4(&bb[2][0], aB + boff + (uint32_t)(16 * CSTRIDE * 2));
            #pragma unroll
            for (int mt = 0; mt < 2; ++mt)
                #pragma unroll
                for (int nt = 0; nt < 4; ++nt)
                    mma_bf16(acc[mt][nt], ah[mt], bb[nt]);
        }
    }

    const int colb = wc * 32 + (lane & 3) * 2;
    const int rowb = m0 + wr * 32 + (lane >> 2);
    #pragma unroll
    for (int mt = 0; mt < 2; ++mt) {
        #pragma unroll
        for (int nt = 0; nt < 4; ++nt) {
            int col = colb + nt * 8;
            float bx = __ldg(&b1[col]), by = __ldg(&b1[col + 1]);
            float2 v0, v1;
            v0.x = fmaxf(acc[mt][nt][0] + bx, 0.f);
            v0.y = fmaxf(acc[mt][nt][1] + by, 0.f);
            v1.x = fmaxf(acc[mt][nt][2] + bx, 0.f);
            v1.y = fmaxf(acc[mt][nt][3] + by, 0.f);
            int row0 = rowb + mt * 16;
            int row1 = row0 + 8;
            if (row0 < M) *(float2*)&Hid[(size_t)row0 * 64 + col] = v0;
            if (row1 < M) *(float2*)&Hid[(size_t)row1 * 64 + col] = v1;
        }
    }
}

// ================= logits + log_softmax (warp per row) =================
__global__ __launch_bounds__(256)
void logits_kernel(const float* __restrict__ hid,
                   const float* __restrict__ w2, const float* __restrict__ b2,
                   float* __restrict__ out)
{
    __shared__ float s_w2[64 * OUT_DIM];
    __shared__ float s_b2[OUT_DIM];
    __shared__ float s_hid[8][64];

    int tid = threadIdx.x;
    for (int i = tid; i < 64 * OUT_DIM; i += 256) s_w2[i] = w2[i];
    if (tid < OUT_DIM) s_b2[tid] = b2[tid];
    __syncthreads();

    int warp = tid >> 5, lane = tid & 31;
    int stride = gridDim.x * 8;
    for (int row = blockIdx.x * 8 + warp; row < N_NODES; row += stride) {
        float2 hv = *(const float2*)&hid[(size_t)row * 64 + lane * 2];
        *(float2*)&s_hid[warp][lane * 2] = hv;
        __syncwarp();
        int o = lane & 15;
        int kbase = (lane >> 4) * 32;
        float part = 0.f;
        #pragma unroll 8
        for (int k = 0; k < 32; ++k)
            part = fmaf(s_hid[warp][kbase + k], s_w2[(kbase + k) * OUT_DIM + o], part);
        part += __shfl_xor_sync(0xffffffffu, part, 16);
        float logit = part + s_b2[o];
        float mx = logit;
        #pragma unroll
        for (int off = 8; off; off >>= 1)
            mx = fmaxf(mx, __shfl_xor_sync(0xffffffffu, mx, off));
        float ex = __expf(logit - mx);
        float sm = ex;
        #pragma unroll
        for (int off = 8; off; off >>= 1)
            sm += __shfl_xor_sync(0xffffffffu, sm, off);
        float res = logit - mx - logf(sm);
        if (lane < 16) out[(size_t)row * OUT_DIM + lane] = res;
        __syncwarp();
    }
}

// ================= GAT aggregation (warp per dst, fp16 xh) =================
__global__ __launch_bounds__(256)
void gat_aggregate(const __half* __restrict__ xh,
                   const float* __restrict__ gat_b,
                   const float* __restrict__ ln_g,
                   const float* __restrict__ ln_b,
                   float* __restrict__ h,
                   __nv_bfloat16* __restrict__ hhi)
{
    int w = (blockIdx.x * blockDim.x + threadIdx.x) >> 5;
    if (w >= N_NODES) return;
    int lane = threadIdx.x & 31;
    int hd = lane >> 2;
    int f = lane * 4;

    float a_d = g_ald[w * NHEAD + hd];
    float e0 = g_als[w * NHEAD + hd] + a_d;
    e0 = fmaxf(e0, 0.2f * e0);
    float m = e0;
    float denom = 1.0f;
    float4 acc;
    {
        uint2 u = *(const uint2*)&xh[(size_t)w * HID + f];
        const __half2* hp = (const __half2*)&u;
        float2 a = __half22float2(hp[0]);
        float2 b = __half22float2(hp[1]);
        acc.x = a.x; acc.y = a.y; acc.z = b.x; acc.w = b.y;
    }

    int beg = g_rowptr[w], end = g_rowptr[w + 1];
    for (int i = beg; i < end; ++i) {
        int s = g_col[i];
        float e2 = g_als[s * NHEAD + hd] + a_d;
        e2 = fmaxf(e2, 0.2f * e2);
        float mn = fmaxf(m, e2);
        float sc = __expf(m - mn);
        float p  = __expf(e2 - mn);
        uint2 u = *(const uint2*)&xh[(size_t)s * HID + f];
        const __half2* hp = (const __half2*)&u;
        float2 va = __half22float2(hp[0]);
        float2 vb = __half22float2(hp[1]);
        acc.x = acc.x * sc + p * va.x;
        acc.y = acc.y * sc + p * va.y;
        acc.z = acc.z * sc + p * vb.x;
        acc.w = acc.w * sc + p * vb.y;
        denom = denom * sc + p;
        m = mn;
    }

    float inv = 1.0f / denom;
    float4 r  = *(const float4*)&h[(size_t)w * HID + f];
    float4 gb = *(const float4*)&gat_b[f];
    float v0 = fmaf(acc.x, inv, gb.x + r.x);
    float v1 = fmaf(acc.y, inv, gb.y + r.y);
    float v2 = fmaf(acc.z, inv, gb.z + r.z);
    float v3 = fmaf(acc.w, inv, gb.w + r.w);

    float sum = v0 + v1 + v2 + v3;
    float sq  = v0 * v0 + v1 * v1 + v2 * v2 + v3 * v3;
    #pragma unroll
    for (int off = 16; off; off >>= 1) {
        sum += __shfl_xor_sync(0xffffffffu, sum, off);
        sq  += __shfl_xor_sync(0xffffffffu, sq,  off);
    }
    float mean = sum * (1.0f / 128.0f);
    float var  = sq  * (1.0f / 128.0f) - mean * mean;
    float rs = rsqrtf(var + 1e-5f);

    float4 g4 = *(const float4*)&ln_g[f];
    float4 b4 = *(const float4*)&ln_b[f];
    float4 o;
    o.x = fmaxf((v0 - mean) * rs * g4.x + b4.x, 0.f);
    o.y = fmaxf((v1 - mean) * rs * g4.y + b4.y, 0.f);
    o.z = fmaxf((v2 - mean) * rs * g4.z + b4.z, 0.f);
    o.w = fmaxf((v3 - mean) * rs * g4.w + b4.w, 0.f);
    *(float4*)&h[(size_t)w * HID + f] = o;

    uint2 uh;
    uh.x = pack_bf2(o.x, o.y);
    uh.y = pack_bf2(o.z, o.w);
    *(uint2*)&hhi[(size_t)w * HID + f] = uh;
}

// ================= launch =================
extern "C" void kernel_launch(void* const* d_in, const int* in_sizes, int n_in,
                              void* d_out, int out_size)
{
    const float* x       = (const float*)d_in[0];
    const int*   ei      = (const int*)  d_in[1];
    const float* proj_w  = (const float*)d_in[2];
    const float* proj_b  = (const float*)d_in[3];
    const float* lin_w   = (const float*)d_in[4];
    const float* att_src = (const float*)d_in[5];
    const float* att_dst = (const float*)d_in[6];
    const float* gat_b   = (const float*)d_in[7];
    const float* ln_g    = (const float*)d_in[8];
    const float* ln_b    = (const float*)d_in[9];
    const float* cls_w1  = (const float*)d_in[10];
    const float* cls_b1  = (const float*)d_in[11];
    const float* cls_w2  = (const float*)d_in[12];
    const float* cls_b2  = (const float*)d_in[13];
    float* out = (float*)d_out;

    const int* src = ei;
    const int* dst = ei + N_EDGES;

    float *h_ptr = nullptr, *hid_ptr = nullptr;
    __half* xhh_ptr = nullptr;
    __nv_bfloat16 *bhi = nullptr, *hhi = nullptr;
    cudaGetSymbolAddress((void**)&h_ptr, g_h);
    cudaGetSymbolAddress((void**)&xhh_ptr, g_xhh);
    cudaGetSymbolAddress((void**)&hid_ptr, g_hid);
    cudaGetSymbolAddress((void**)&bhi, g_bhi);
    cudaGetSymbolAddress((void**)&hhi, g_hhi);

    const int GEMM_GRID = (N_NODES + 127) / 128;  // 391
    const int SCAN_BLOCKS = (N_NODES + 1 + 1023) / 1024;  // 49

    // my#1-3: conversions + independent CSR prefix
    conv_all_kernel<<<128, 256>>>(proj_w, lin_w, cls_w1);
    zero_rowptr_kernel<<<(N_NODES + 1 + 255) / 256, 256>>>();
    hist_kernel<<<(N_EDGES + 255) / 256, 256>>>(dst);

    // my#4 (ncu-profiled): projection GEMM  h = relu(x @ proj_w + b)
    gemm_mma<0><<<GEMM_GRID, 256>>>(
        x, nullptr, bhi + B_PROJ_OFF, proj_b,
        nullptr, nullptr, h_ptr, nullptr, hhi, nullptr, N_NODES, IN_DIM);

    // layer-0 GEMM + fused attention logits (fp16 xh out)
    gemm_mma<1><<<GEMM_GRID, 256>>>(
        hhi, nullptr, bhi + B_LIN_OFF, nullptr,
        att_src, att_dst, nullptr, xhh_ptr, nullptr, nullptr, N_NODES, HID);

    // CSR build tail
    scan_block_kernel<<<SCAN_BLOCKS, 1024>>>();
    scan_sums_kernel<<<1, 64>>>(SCAN_BLOCKS);
    scan_add_kernel<<<SCAN_BLOCKS, 1024>>>();
    scatter_kernel<<<(N_EDGES + 255) / 256, 256>>>(src, dst);

    // layer 0 aggregation
    gat_aggregate<<<N_NODES / 8, 256>>>(
        xhh_ptr, gat_b, ln_g, ln_b, h_ptr, hhi);

    // layers 1..2
    for (int l = 1; l < NLAYER; ++l) {
        gemm_mma<1><<<GEMM_GRID, 256>>>(
            hhi, nullptr, bhi + B_LIN_OFF + l * 128 * HID,
            nullptr, att_src + l * NHEAD * CH, att_dst + l * NHEAD * CH,
            nullptr, xhh_ptr, nullptr, nullptr, N_NODES, HID);
        gat_aggregate<<<N_NODES / 8, 256>>>(
            xhh_ptr, gat_b + l * HID, ln_g + l * HID, ln_b + l * HID, h_ptr, hhi);
    }

    // classifier: hidden layer on tensor cores, then tiny logits+log_softmax
    cls_hid_gemm<<<GEMM_GRID, 256>>>(hhi, bhi + B_CLS_OFF, cls_b1, hid_ptr, N_NODES);
    logits_kernel<<<592, 256>>>(hid_ptr, cls_w2, cls_b2, out);
}

// round 17
// speedup vs baseline: 1.2933x; 1.0564x over previous
#include <cuda_runtime.h>
#include <cuda_bf16.h>
#include <cuda_fp16.h>
#include <math.h>
#include <stdint.h>

#define N_NODES 50000
#define N_EDGES 500000
#define IN_DIM  384
#define HID     128
#define NHEAD   8
#define CH      16
#define NLAYER  3
#define OUT_DIM 16

// ================= device scratch =================
__device__ int   g_rowptr[N_NODES + 1];
__device__ int   g_cursor[N_NODES];
__device__ int   g_col[N_EDGES];
__device__ int   g_bsums[64];
__device__ float g_h[(size_t)N_NODES * HID];
__device__ __half g_xhh[(size_t)N_NODES * HID];   // fp16 xh (GEMM out, aggregate in)
__device__ float g_als[N_NODES * NHEAD];
__device__ float g_ald[N_NODES * NHEAD];
__device__ float g_hid[(size_t)N_NODES * 64];
__device__ __nv_bfloat16 g_hhi[(size_t)N_NODES * HID];
// bf16 weights (hi only), K-major
#define B_PROJ_OFF 0
#define B_LIN_OFF  (128 * IN_DIM)
#define B_CLS_OFF  (B_LIN_OFF + NLAYER * 128 * HID)
__device__ __nv_bfloat16 g_bhi[128 * IN_DIM + NLAYER * 128 * HID + 64 * HID];

// ================= CSR build =================
__global__ void zero_rowptr_kernel() {
    int i = blockIdx.x * blockDim.x + threadIdx.x;
    if (i <= N_NODES) g_rowptr[i] = 0;
}
__global__ void hist_kernel(const int* __restrict__ dst) {
    int i = blockIdx.x * blockDim.x + threadIdx.x;
    if (i < N_EDGES) atomicAdd(&g_rowptr[dst[i] + 1], 1);
}
__global__ void scan_block_kernel() {
    __shared__ int s[1024];
    const int n = N_NODES + 1;
    int t = threadIdx.x;
    int gid = blockIdx.x * 1024 + t;
    s[t] = (gid < n) ? g_rowptr[gid] : 0;
    __syncthreads();
    #pragma unroll
    for (int off = 1; off < 1024; off <<= 1) {
        int v = (t >= off) ? s[t - off] : 0;
        __syncthreads();
        s[t] += v;
        __syncthreads();
    }
    if (gid < n) g_rowptr[gid] = s[t];
    if (t == 1023) g_bsums[blockIdx.x] = s[1023];
}
__global__ void scan_sums_kernel(int nb) {
    __shared__ int ws[2];
    int t = threadIdx.x;
    int lane = t & 31, w = t >> 5;
    int v = (t < nb) ? g_bsums[t] : 0;
    int x = v;
    #pragma unroll
    for (int off = 1; off < 32; off <<= 1) {
        int y = __shfl_up_sync(0xffffffffu, x, off);
        if (lane >= off) x += y;
    }
    if (lane == 31) ws[w] = x;
    __syncthreads();
    if (w == 1) x += ws[0];
    if (t < nb) g_bsums[t] = x - v;   // exclusive
}
__global__ void scan_add_kernel() {
    const int n = N_NODES + 1;
    int gid = blockIdx.x * 1024 + threadIdx.x;
    if (gid < n) {
        int v = g_rowptr[gid] + g_bsums[blockIdx.x];
        g_rowptr[gid] = v;
        if (gid < N_NODES) g_cursor[gid] = v;
    }
}
__global__ void scatter_kernel(const int* __restrict__ src, const int* __restrict__ dst) {
    int i = blockIdx.x * blockDim.x + threadIdx.x;
    if (i < N_EDGES) {
        int d = dst[i];
        int pos = atomicAdd(&g_cursor[d], 1);
        g_col[pos] = src[i];
    }
}

// ================= helpers =================
__device__ __forceinline__ uint32_t pack_bf2(float x, float y) {
    __nv_bfloat162 t = __floats2bfloat162_rn(x, y);
    return *reinterpret_cast<uint32_t*>(&t);
}

// ONE launch converts all weights (hi only): proj, lin[3], cls_w1
__global__ void conv_all_kernel(const float* __restrict__ proj_w,
                                const float* __restrict__ lin_w,
                                const float* __restrict__ cls_w1) {
    const int T1 = IN_DIM * 128;
    const int T2 = T1 + NLAYER * HID * 128;
    const int TOT = T2 + HID * 64;
    for (int i = blockIdx.x * blockDim.x + threadIdx.x; i < TOT; i += gridDim.x * blockDim.x) {
        if (i < T1) {
            int k = i >> 7, n = i & 127;
            float v = proj_w[(size_t)k * 128 + n];
            g_bhi[B_PROJ_OFF + (size_t)n * IN_DIM + k] = __float2bfloat16(v);
        } else if (i < T2) {
            int j = i - T1;
            int l = j / (HID * 128);
            j -= l * HID * 128;
            int k = j >> 7, n = j & 127;
            float v = lin_w[(size_t)l * HID * HID + (size_t)k * 128 + n];
            g_bhi[B_LIN_OFF + l * 128 * HID + (size_t)n * HID + k] = __float2bfloat16(v);
        } else {
            int j = i - T2;              // w1 [128][64]
            int k = j >> 6, n = j & 63;
            float v = cls_w1[(size_t)k * 64 + n];
            g_bhi[B_CLS_OFF + (size_t)n * HID + k] = __float2bfloat16(v);
        }
    }
}

// ================= HMMA GEMM, R10 config ==========
// C[M,128] = A[M,K] @ W.  Block 128x128, 8 warps 4(m)x2(n), K-tile 32.
// MODE 0 (proj):  2-term A split (Ah*B + Al*B); out fp32 C + bf16 hi split.
// MODE 1 (layer): 1-term bf16 A; out fp16 Cxh + fused attn logits.
#define ASTRIDE 40   // bf16 elems per smem row (pad -> conflict-free)

__device__ __forceinline__ uint32_t smem_addr_u32(const void* p) {
    return (uint32_t)__cvta_generic_to_shared(p);
}
__device__ __forceinline__ void ldsm_x4(uint32_t* r, uint32_t addr) {
    asm volatile("ldmatrix.sync.aligned.m8n8.x4.shared.b16 {%0,%1,%2,%3}, [%4];"
                 : "=r"(r[0]), "=r"(r[1]), "=r"(r[2]), "=r"(r[3]) : "r"(addr));
}
__device__ __forceinline__ void mma_bf16(float* d, const uint32_t* a, const uint32_t* b) {
    asm volatile(
        "mma.sync.aligned.m16n8k16.row.col.f32.bf16.bf16.f32 "
        "{%0,%1,%2,%3}, {%4,%5,%6,%7}, {%8,%9}, {%0,%1,%2,%3};"
        : "+f"(d[0]), "+f"(d[1]), "+f"(d[2]), "+f"(d[3])
        : "r"(a[0]), "r"(a[1]), "r"(a[2]), "r"(a[3]), "r"(b[0]), "r"(b[1]));
}

template<int MODE>
__global__ __launch_bounds__(256, 2)
void gemm_mma(const void* __restrict__ A_, const __nv_bfloat16* __restrict__ Alo_,
              const __nv_bfloat16* __restrict__ Bhi,
              const float* __restrict__ bias,
              const float* __restrict__ att_s, const float* __restrict__ att_d,
              float* __restrict__ C, __half* __restrict__ Cxh,
              __nv_bfloat16* __restrict__ Chi,
              int M, int K)
{
    __shared__ __align__(16) __nv_bfloat16 sAh[128 * ASTRIDE];
    __shared__ __align__(16) __nv_bfloat16 sAl[(MODE == 0) ? 128 * ASTRIDE : 1];
    __shared__ __align__(16) __nv_bfloat16 sBh[128 * ASTRIDE];

    const int tid  = threadIdx.x;
    const int wid  = tid >> 5, lane = tid & 31;
    const int wr   = wid >> 1, wc = wid & 1;     // warp 4x2 grid
    const int m0   = blockIdx.x * 128;

    const int r  = tid >> 1;
    const int kh = (tid & 1) * 16;
    const int grow = m0 + r;
    const bool valid = grow < M;

    float acc[2][8][4];
    #pragma unroll
    for (int mt = 0; mt < 2; ++mt)
        #pragma unroll
        for (int nt = 0; nt < 8; ++nt)
            #pragma unroll
            for (int j = 0; j < 4; ++j) acc[mt][nt][j] = 0.f;

    const uint32_t aAh = smem_addr_u32(sAh);
    const uint32_t aAl = smem_addr_u32(sAl);
    const uint32_t aBh = smem_addr_u32(sBh);
    const int a_row = wr * 32 + (lane & 15);
    const int a_kof = (lane >> 4) * 8;
    const int b_row = wc * 64 + (lane & 7) + ((lane >> 4) << 3);
    const int b_kof = ((lane >> 3) & 1) * 8;

    const int nkt = K >> 5;
    for (int kt = 0; kt < nkt; ++kt) {
        __syncthreads();
        // ---- fill A ----
        if (MODE == 0) {
            const float* ap = (const float*)A_ + (size_t)grow * K + kt * 32 + kh;
            float4 f0, f1, f2, f3;
            if (valid) {
                f0 = *(const float4*)(ap + 0);
                f1 = *(const float4*)(ap + 4);
                f2 = *(const float4*)(ap + 8);
                f3 = *(const float4*)(ap + 12);
            } else {
                f0 = make_float4(0.f, 0.f, 0.f, 0.f);
                f1 = f0; f2 = f0; f3 = f0;
            }
            uint4 uh0, uh1, ul0, ul1;
            uh0.x = pack_bf2(f0.x, f0.y); uh0.y = pack_bf2(f0.z, f0.w);
            uh0.z = pack_bf2(f1.x, f1.y); uh0.w = pack_bf2(f1.z, f1.w);
            uh1.x = pack_bf2(f2.x, f2.y); uh1.y = pack_bf2(f2.z, f2.w);
            uh1.z = pack_bf2(f3.x, f3.y); uh1.w = pack_bf2(f3.z, f3.w);
            const __nv_bfloat162* hp0 = (const __nv_bfloat162*)&uh0;
            const __nv_bfloat162* hp1 = (const __nv_bfloat162*)&uh1;
            float2 h;
            h = __bfloat1622float2(hp0[0]); ul0.x = pack_bf2(f0.x - h.x, f0.y - h.y);
            h = __bfloat1622float2(hp0[1]); ul0.y = pack_bf2(f0.z - h.x, f0.w - h.y);
            h = __bfloat1622float2(hp0[2]); ul0.z = pack_bf2(f1.x - h.x, f1.y - h.y);
            h = __bfloat1622float2(hp0[3]); ul0.w = pack_bf2(f1.z - h.x, f1.w - h.y);
            h = __bfloat1622float2(hp1[0]); ul1.x = pack_bf2(f2.x - h.x, f2.y - h.y);
            h = __bfloat1622float2(hp1[1]); ul1.y = pack_bf2(f2.z - h.x, f2.w - h.y);
            h = __bfloat1622float2(hp1[2]); ul1.z = pack_bf2(f3.x - h.x, f3.y - h.y);
            h = __bfloat1622float2(hp1[3]); ul1.w = pack_bf2(f3.z - h.x, f3.w - h.y);
            *(uint4*)&sAh[r * ASTRIDE + kh]     = uh0;
            *(uint4*)&sAh[r * ASTRIDE + kh + 8] = uh1;
            *(uint4*)&sAl[r * ASTRIDE + kh]     = ul0;
            *(uint4*)&sAl[r * ASTRIDE + kh + 8] = ul1;
        } else {
            const uint4 z = make_uint4(0u, 0u, 0u, 0u);
            const __nv_bfloat16* ah = (const __nv_bfloat16*)A_ + (size_t)grow * K + kt * 32 + kh;
            uint4 h0 = valid ? *(const uint4*)(ah)     : z;
            uint4 h1 = valid ? *(const uint4*)(ah + 8) : z;
            *(uint4*)&sAh[r * ASTRIDE + kh]     = h0;
            *(uint4*)&sAh[r * ASTRIDE + kh + 8] = h1;
        }
        // ---- fill B (bf16, K-major) ----
        {
            const __nv_bfloat16* bh = Bhi + (size_t)r * K + kt * 32 + kh;
            *(uint4*)&sBh[r * ASTRIDE + kh]     = *(const uint4*)(bh + 0);
            *(uint4*)&sBh[r * ASTRIDE + kh + 8] = *(const uint4*)(bh + 8);
        }
        __syncthreads();

        #pragma unroll
        for (int ks = 0; ks < 2; ++ks) {
            const uint32_t aoff = (uint32_t)((a_row * ASTRIDE + ks * 16 + a_kof) * 2);
            const uint32_t boff = (uint32_t)((b_row * ASTRIDE + ks * 16 + b_kof) * 2);
            uint32_t ah[2][4], al[2][4], bb[8][2];
            ldsm_x4(ah[0], aAh + aoff);
            ldsm_x4(ah[1], aAh + aoff + 16 * ASTRIDE * 2);
            if (MODE == 0) {
                ldsm_x4(al[0], aAl + aoff);
                ldsm_x4(al[1], aAl + aoff + 16 * ASTRIDE * 2);
            }
            #pragma unroll
            for (int p = 0; p < 4; ++p)
                ldsm_x4(&bb[p * 2][0], aBh + boff + (uint32_t)(p * 16 * ASTRIDE * 2));
            #pragma unroll
            for (int mt = 0; mt < 2; ++mt)
                #pragma unroll
                for (int nt = 0; nt < 8; ++nt) {
                    mma_bf16(acc[mt][nt], ah[mt], bb[nt]);
                    if (MODE == 0) mma_bf16(acc[mt][nt], al[mt], bb[nt]);
                }
        }
    }

    // ---- epilogue ----
    const int colb = wc * 64 + (lane & 3) * 2;
    const int rowb = m0 + wr * 32 + (lane >> 2);
    #pragma unroll
    for (int mt = 0; mt < 2; ++mt) {
        #pragma unroll
        for (int nt = 0; nt < 8; ++nt) {
            int col = colb + nt * 8;
            float2 v0, v1;
            v0.x = acc[mt][nt][0]; v0.y = acc[mt][nt][1];
            v1.x = acc[mt][nt][2]; v1.y = acc[mt][nt][3];
            int row0 = rowb + mt * 16;
            int row1 = row0 + 8;
            if (MODE == 0) {
                float bx = __ldg(&bias[col]), by = __ldg(&bias[col + 1]);
                v0.x = fmaxf(v0.x + bx, 0.f); v0.y = fmaxf(v0.y + by, 0.f);
                v1.x = fmaxf(v1.x + bx, 0.f); v1.y = fmaxf(v1.y + by, 0.f);
                acc[mt][nt][0] = v0.x; acc[mt][nt][1] = v0.y;
                acc[mt][nt][2] = v1.x; acc[mt][nt][3] = v1.y;
                if (row0 < M) {
                    *(float2*)&C[(size_t)row0 * 128 + col] = v0;
                    *(uint32_t*)&Chi[(size_t)row0 * 128 + col] = pack_bf2(v0.x, v0.y);
                }
                if (row1 < M) {
                    *(float2*)&C[(size_t)row1 * 128 + col] = v1;
                    *(uint32_t*)&Chi[(size_t)row1 * 128 + col] = pack_bf2(v1.x, v1.y);
                }
            } else {
                if (row0 < M)
                    *(__half2*)&Cxh[(size_t)row0 * 128 + col] = __floats2half2_rn(v0.x, v0.y);
                if (row1 < M)
                    *(__half2*)&Cxh[(size_t)row1 * 128 + col] = __floats2half2_rn(v1.x, v1.y);
            }
        }
    }

    if (MODE == 1) {
        // ---- fused attention logits (att vectors hoisted) ----
        float as_r[4][2][2], ad_r[4][2][2];   // [hl][jb][ntb]
        #pragma unroll
        for (int hl = 0; hl < 4; ++hl)
            #pragma unroll
            for (int jb = 0; jb < 2; ++jb)
                #pragma unroll
                for (int ntb = 0; ntb < 2; ++ntb) {
                    int cmod = (lane & 3) * 2 + jb + 8 * ntb;
                    as_r[hl][jb][ntb] = __ldg(&att_s[(wc * 4 + hl) * 16 + cmod]);
                    ad_r[hl][jb][ntb] = __ldg(&att_d[(wc * 4 + hl) * 16 + cmod]);
                }
        #pragma unroll
        for (int mt = 0; mt < 2; ++mt) {
            float ss[2][4], dd[2][4];
            #pragma unroll
            for (int a = 0; a < 2; ++a)
                #pragma unroll
                for (int b = 0; b < 4; ++b) { ss[a][b] = 0.f; dd[a][b] = 0.f; }
            #pragma unroll
            for (int nt = 0; nt < 8; ++nt) {
                int hl = nt >> 1, ntb = nt & 1;
                #pragma unroll
                for (int j = 0; j < 4; ++j) {
                    int jb = j & 1, rj = j >> 1;
                    ss[rj][hl] = fmaf(acc[mt][nt][j], as_r[hl][jb][ntb], ss[rj][hl]);
                    dd[rj][hl] = fmaf(acc[mt][nt][j], ad_r[hl][jb][ntb], dd[rj][hl]);
                }
            }
            #pragma unroll
            for (int rj = 0; rj < 2; ++rj)
                #pragma unroll
                for (int hl = 0; hl < 4; ++hl) {
                    ss[rj][hl] += __shfl_xor_sync(0xffffffffu, ss[rj][hl], 1);
                    ss[rj][hl] += __shfl_xor_sync(0xffffffffu, ss[rj][hl], 2);
                    dd[rj][hl] += __shfl_xor_sync(0xffffffffu, dd[rj][hl], 1);
                    dd[rj][hl] += __shfl_xor_sync(0xffffffffu, dd[rj][hl], 2);
                }
            if ((lane & 3) == 0) {
                #pragma unroll
                for (int rj = 0; rj < 2; ++rj) {
                    int row = rowb + mt * 16 + rj * 8;
                    if (row < M) {
                        #pragma unroll
                        for (int hl = 0; hl < 4; ++hl) {
                            g_als[row * 8 + wc * 4 + hl] = ss[rj][hl];
                            g_ald[row * 8 + wc * 4 + hl] = dd[rj][hl];
                        }
                    }
                }
            }
        }
    }
}

// ================= classifier hidden layer via HMMA (1-term bf16) ======
#define CSTRIDE 40
__global__ __launch_bounds__(256, 2)
void cls_hid_gemm(const __nv_bfloat16* __restrict__ Ahi,
                  const __nv_bfloat16* __restrict__ Bh, const float* __restrict__ b1,
                  float* __restrict__ Hid, int M)
{
    __shared__ __align__(16) __nv_bfloat16 sAh[128 * CSTRIDE];
    __shared__ __align__(16) __nv_bfloat16 sB[64 * CSTRIDE];

    const int tid = threadIdx.x;
    const int wid = tid >> 5, lane = tid & 31;
    const int wr = wid >> 1, wc = wid & 1;
    const int m0 = blockIdx.x * 128;
    const int r = tid >> 1;
    const int kh = (tid & 1) * 16;
    const int grow = m0 + r;
    const bool valid = grow < M;

    float acc[2][4][4];
    #pragma unroll
    for (int mt = 0; mt < 2; ++mt)
        #pragma unroll
        for (int nt = 0; nt < 4; ++nt)
            #pragma unroll
            for (int j = 0; j < 4; ++j) acc[mt][nt][j] = 0.f;

    const uint32_t aAh = smem_addr_u32(sAh);
    const uint32_t aB  = smem_addr_u32(sB);
    const int a_row = wr * 32 + (lane & 15);
    const int a_kof = (lane >> 4) * 8;
    const int b_row = wc * 32 + (lane & 7) + ((lane >> 4) << 3);
    const int b_kof = ((lane >> 3) & 1) * 8;

    #pragma unroll
    for (int kt = 0; kt < 4; ++kt) {
        __syncthreads();
        {
            const uint4 z = make_uint4(0u, 0u, 0u, 0u);
            const __nv_bfloat16* ah = Ahi + (size_t)grow * HID + kt * 32 + kh;
            uint4 h0 = valid ? *(const uint4*)(ah)     : z;
            uint4 h1 = valid ? *(const uint4*)(ah + 8) : z;
            *(uint4*)&sAh[r * CSTRIDE + kh]     = h0;
            *(uint4*)&sAh[r * CSTRIDE + kh + 8] = h1;
        }
        if (tid < 128) {
            int br = tid >> 1;
            const __nv_bfloat16* bp = Bh + (size_t)br * HID + kt * 32 + kh;
            *(uint4*)&sB[br * CSTRIDE + kh]     = *(const uint4*)(bp + 0);
            *(uint4*)&sB[br * CSTRIDE + kh + 8] = *(const uint4*)(bp + 8);
        }
        __syncthreads();

        #pragma unroll
        for (int ks = 0; ks < 2; ++ks) {
            const uint32_t aoff = (uint32_t)((a_row * CSTRIDE + ks * 16 + a_kof) * 2);
            const uint32_t boff = (uint32_t)((b_row * CSTRIDE + ks * 16 + b_kof) * 2);
            uint32_t ah[2][4], bb[4][2];
            ldsm_x4(ah[0], aAh + aoff);
            ldsm_x4(ah[1], aAh + aoff + 16 * CSTRIDE * 2);
            ldsm_x4(&bb[0][0], aB + boff);
            ldsm_x4(&bb[2][0], aB + boff + (uint32_t)(16 * CSTRIDE * 2));
            #pragma unroll
            for (int mt = 0; mt < 2; ++mt)
                #pragma unroll
                for (int nt = 0; nt < 4; ++nt)
                    mma_bf16(acc[mt][nt], ah[mt], bb[nt]);
        }
    }

    const int colb = wc * 32 + (lane & 3) * 2;
    const int rowb = m0 + wr * 32 + (lane >> 2);
    #pragma unroll
    for (int mt = 0; mt < 2; ++mt) {
        #pragma unroll
        for (int nt = 0; nt < 4; ++nt) {
            int col = colb + nt * 8;
            float bx = __ldg(&b1[col]), by = __ldg(&b1[col + 1]);
            float2 v0, v1;
            v0.x = fmaxf(acc[mt][nt][0] + bx, 0.f);
            v0.y = fmaxf(acc[mt][nt][1] + by, 0.f);
            v1.x = fmaxf(acc[mt][nt][2] + bx, 0.f);
            v1.y = fmaxf(acc[mt][nt][3] + by, 0.f);
            int row0 = rowb + mt * 16;
            int row1 = row0 + 8;
            if (row0 < M) *(float2*)&Hid[(size_t)row0 * 64 + col] = v0;
            if (row1 < M) *(float2*)&Hid[(size_t)row1 * 64 + col] = v1;
        }
    }
}

// ================= logits + log_softmax (warp per row) =================
__global__ __launch_bounds__(256)
void logits_kernel(const float* __restrict__ hid,
                   const float* __restrict__ w2, const float* __restrict__ b2,
                   float* __restrict__ out)
{
    __shared__ float s_w2[64 * OUT_DIM];
    __shared__ float s_b2[OUT_DIM];
    __shared__ float s_hid[8][64];

    int tid = threadIdx.x;
    for (int i = tid; i < 64 * OUT_DIM; i += 256) s_w2[i] = w2[i];
    if (tid < OUT_DIM) s_b2[tid] = b2[tid];
    __syncthreads();

    int warp = tid >> 5, lane = tid & 31;
    int stride = gridDim.x * 8;
    for (int row = blockIdx.x * 8 + warp; row < N_NODES; row += stride) {
        float2 hv = *(const float2*)&hid[(size_t)row * 64 + lane * 2];
        *(float2*)&s_hid[warp][lane * 2] = hv;
        __syncwarp();
        int o = lane & 15;
        int kbase = (lane >> 4) * 32;
        float part = 0.f;
        #pragma unroll 8
        for (int k = 0; k < 32; ++k)
            part = fmaf(s_hid[warp][kbase + k], s_w2[(kbase + k) * OUT_DIM + o], part);
        part += __shfl_xor_sync(0xffffffffu, part, 16);
        float logit = part + s_b2[o];
        float mx = logit;
        #pragma unroll
        for (int off = 8; off; off >>= 1)
            mx = fmaxf(mx, __shfl_xor_sync(0xffffffffu, mx, off));
        float ex = __expf(logit - mx);
        float sm = ex;
        #pragma unroll
        for (int off = 8; off; off >>= 1)
            sm += __shfl_xor_sync(0xffffffffu, sm, off);
        float res = logit - mx - logf(sm);
        if (lane < 16) out[(size_t)row * OUT_DIM + lane] = res;
        __syncwarp();
    }
}

// ================= GAT aggregation (warp per dst, fp16 xh) =================
// direct exp (no online max): logits are O(1), no overflow risk; softmax is
// shift-invariant so result is identical up to fp rounding. This removes the
// serial rescale chain between edges -> accumulation FMAs pipeline freely.
__global__ __launch_bounds__(256)
void gat_aggregate(const __half* __restrict__ xh,
                   const float* __restrict__ gat_b,
                   const float* __restrict__ ln_g,
                   const float* __restrict__ ln_b,
                   float* __restrict__ h,
                   __nv_bfloat16* __restrict__ hhi)
{
    int w = (blockIdx.x * blockDim.x + threadIdx.x) >> 5;
    if (w >= N_NODES) return;
    int lane = threadIdx.x & 31;
    int hd = lane >> 2;
    int f = lane * 4;

    float a_d = g_ald[w * NHEAD + hd];
    float e0 = g_als[w * NHEAD + hd] + a_d;
    e0 = fmaxf(e0, 0.2f * e0);
    float p0 = __expf(e0);
    float denom = p0;
    float4 acc;
    {
        uint2 u = *(const uint2*)&xh[(size_t)w * HID + f];
        const __half2* hp = (const __half2*)&u;
        float2 a = __half22float2(hp[0]);
        float2 b = __half22float2(hp[1]);
        acc.x = p0 * a.x; acc.y = p0 * a.y; acc.z = p0 * b.x; acc.w = p0 * b.y;
    }

    int beg = g_rowptr[w], end = g_rowptr[w + 1];
    for (int i = beg; i < end; ++i) {
        int s = g_col[i];
        float e2 = g_als[s * NHEAD + hd] + a_d;
        e2 = fmaxf(e2, 0.2f * e2);
        float p = __expf(e2);
        uint2 u = *(const uint2*)&xh[(size_t)s * HID + f];
        const __half2* hp = (const __half2*)&u;
        float2 va = __half22float2(hp[0]);
        float2 vb = __half22float2(hp[1]);
        acc.x = fmaf(p, va.x, acc.x);
        acc.y = fmaf(p, va.y, acc.y);
        acc.z = fmaf(p, vb.x, acc.z);
        acc.w = fmaf(p, vb.y, acc.w);
        denom += p;
    }

    float inv = 1.0f / denom;
    float4 r  = *(const float4*)&h[(size_t)w * HID + f];
    float4 gb = *(const float4*)&gat_b[f];
    float v0 = fmaf(acc.x, inv, gb.x + r.x);
    float v1 = fmaf(acc.y, inv, gb.y + r.y);
    float v2 = fmaf(acc.z, inv, gb.z + r.z);
    float v3 = fmaf(acc.w, inv, gb.w + r.w);

    float sum = v0 + v1 + v2 + v3;
    float sq  = v0 * v0 + v1 * v1 + v2 * v2 + v3 * v3;
    #pragma unroll
    for (int off = 16; off; off >>= 1) {
        sum += __shfl_xor_sync(0xffffffffu, sum, off);
        sq  += __shfl_xor_sync(0xffffffffu, sq,  off);
    }
    float mean = sum * (1.0f / 128.0f);
    float var  = sq  * (1.0f / 128.0f) - mean * mean;
    float rs = rsqrtf(var + 1e-5f);

    float4 g4 = *(const float4*)&ln_g[f];
    float4 b4 = *(const float4*)&ln_b[f];
    float4 o;
    o.x = fmaxf((v0 - mean) * rs * g4.x + b4.x, 0.f);
    o.y = fmaxf((v1 - mean) * rs * g4.y + b4.y, 0.f);
    o.z = fmaxf((v2 - mean) * rs * g4.z + b4.z, 0.f);
    o.w = fmaxf((v3 - mean) * rs * g4.w + b4.w, 0.f);
    *(float4*)&h[(size_t)w * HID + f] = o;

    uint2 uh;
    uh.x = pack_bf2(o.x, o.y);
    uh.y = pack_bf2(o.z, o.w);
    *(uint2*)&hhi[(size_t)w * HID + f] = uh;
}

// ================= launch =================
extern "C" void kernel_launch(void* const* d_in, const int* in_sizes, int n_in,
                              void* d_out, int out_size)
{
    const float* x       = (const float*)d_in[0];
    const int*   ei      = (const int*)  d_in[1];
    const float* proj_w  = (const float*)d_in[2];
    const float* proj_b  = (const float*)d_in[3];
    const float* lin_w   = (const float*)d_in[4];
    const float* att_src = (const float*)d_in[5];
    const float* att_dst = (const float*)d_in[6];
    const float* gat_b   = (const float*)d_in[7];
    const float* ln_g    = (const float*)d_in[8];
    const float* ln_b    = (const float*)d_in[9];
    const float* cls_w1  = (const float*)d_in[10];
    const float* cls_b1  = (const float*)d_in[11];
    const float* cls_w2  = (const float*)d_in[12];
    const float* cls_b2  = (const float*)d_in[13];
    float* out = (float*)d_out;

    const int* src = ei;
    const int* dst = ei + N_EDGES;

    float *h_ptr = nullptr, *hid_ptr = nullptr;
    __half* xhh_ptr = nullptr;
    __nv_bfloat16 *bhi = nullptr, *hhi = nullptr;
    cudaGetSymbolAddress((void**)&h_ptr, g_h);
    cudaGetSymbolAddress((void**)&xhh_ptr, g_xhh);
    cudaGetSymbolAddress((void**)&hid_ptr, g_hid);
    cudaGetSymbolAddress((void**)&bhi, g_bhi);
    cudaGetSymbolAddress((void**)&hhi, g_hhi);

    const int GEMM_GRID = (N_NODES + 127) / 128;  // 391
    const int SCAN_BLOCKS = (N_NODES + 1 + 1023) / 1024;  // 49

    // my#1-3: conversions + independent CSR prefix
    conv_all_kernel<<<128, 256>>>(proj_w, lin_w, cls_w1);
    zero_rowptr_kernel<<<(N_NODES + 1 + 255) / 256, 256>>>();
    hist_kernel<<<(N_EDGES + 255) / 256, 256>>>(dst);

    // my#4 (ncu-profiled): projection GEMM  h = relu(x @ proj_w + b)
    gemm_mma<0><<<GEMM_GRID, 256>>>(
        x, nullptr, bhi + B_PROJ_OFF, proj_b,
        nullptr, nullptr, h_ptr, nullptr, hhi, N_NODES, IN_DIM);

    // layer-0 GEMM + fused attention logits (fp16 xh out)
    gemm_mma<1><<<GEMM_GRID, 256>>>(
        hhi, nullptr, bhi + B_LIN_OFF, nullptr,
        att_src, att_dst, nullptr, xhh_ptr, nullptr, N_NODES, HID);

    // CSR build tail
    scan_block_kernel<<<SCAN_BLOCKS, 1024>>>();
    scan_sums_kernel<<<1, 64>>>(SCAN_BLOCKS);
    scan_add_kernel<<<SCAN_BLOCKS, 1024>>>();
    scatter_kernel<<<(N_EDGES + 255) / 256, 256>>>(src, dst);

    // layer 0 aggregation
    gat_aggregate<<<N_NODES / 8, 256>>>(
        xhh_ptr, gat_b, ln_g, ln_b, h_ptr, hhi);

    // layers 1..2
    for (int l = 1; l < NLAYER; ++l) {
        gemm_mma<1><<<GEMM_GRID, 256>>>(
            hhi, nullptr, bhi + B_LIN_OFF + l * 128 * HID,
            nullptr, att_src + l * NHEAD * CH, att_dst + l * NHEAD * CH,
            nullptr, xhh_ptr, nullptr, N_NODES, HID);
        gat_aggregate<<<N_NODES / 8, 256>>>(
            xhh_ptr, gat_b + l * HID, ln_g + l * HID, ln_b + l * HID, h_ptr, hhi);
    }

    // classifier: hidden layer on tensor cores, then tiny logits+log_softmax
    cls_hid_gemm<<<GEMM_GRID, 256>>>(hhi, bhi + B_CLS_OFF, cls_b1, hid_ptr, N_NODES);
    logits_kernel<<<592, 256>>>(hid_ptr, cls_w2, cls_b2, out);
}